// round 13
// baseline (speedup 1.0000x reference)
#include <cuda_runtime.h>
#include <cuda_bf16.h>
#include <cuda_fp16.h>
#include <cstdint>
#include <math.h>

#define DEV __device__ __forceinline__

// ---------------- problem constants ----------------
// B=8, C=512, H=W=16, L=256, dim=128, chs=1024
// d_inner=2048, d_state=16, d_conv=4, dt_rank=64, 8 branches

// ---------------- scratch (device globals) ----------
__device__ float g_pool[8 * 512 * 275];
__device__ float g_cbr [8 * 128 * 275];
__device__ float g_p0map[8 * 128 * 256];
__device__ float g_p0  [8 * 128];
__device__ float g_xcT [8 * 256 * 1024];
__device__ float g_gw  [64];
__device__ float g_xdbl[8 * 8 * 256 * 96];         // x_proj output fp32 (B,C used by scan)

// fp16 operands / intermediates
__device__ __half g_xzf[8 * 8 * 256 * 4096];       // in_proj output (u|z) fp16
__device__ __half g_ysf[8 * 8 * 256 * 1024];       // out_proj output fp16
__device__ __half g_dtf[8 * 8 * 256 * 2048];       // softplus(dt) fp16
__device__ __half g_xgf[8 * 8 * 256 * 1024];       // fdgate out (single fp16)
__device__ __half g_y2f[8 * 8 * 256 * 2048];       // scan out (single fp16)
__device__ __half g_iwf[8 * 4096 * 1024];          // in_w fp16
__device__ __half g_owf[8 * 1024 * 2048];          // out_w fp16
__device__ __half g_uh [8 * 8 * 256 * 2048];       // u hi
__device__ __half g_ul [8 * 8 * 256 * 2048];       // u lo
__device__ __half g_xpwh[8 * 96 * 2048];           // xp_w hi
__device__ __half g_xpwl[8 * 96 * 2048];           // xp_w lo
__device__ __half g_dtwh[8 * 2048 * 64];           // dtp_w hi
__device__ __half g_dtwl[8 * 2048 * 64];           // dtp_w lo
__device__ __half g_xdh[8 * 8 * 256 * 64];         // xdbl[:, :64] hi (compact)
__device__ __half g_xdl[8 * 8 * 256 * 64];         // xdbl[:, :64] lo (compact)

// ---------------- helpers ----------------
DEV float block_sum(float v, float* red) {
    int lane = threadIdx.x & 31, wid = threadIdx.x >> 5;
#pragma unroll
    for (int o = 16; o > 0; o >>= 1) v += __shfl_xor_sync(0xffffffffu, v, o);
    if (lane == 0) red[wid] = v;
    __syncthreads();
    if (wid == 0) {
        float w = (lane < 8) ? red[lane] : 0.f;
#pragma unroll
        for (int o = 4; o > 0; o >>= 1) w += __shfl_xor_sync(0xffffffffu, w, o);
        if (lane == 0) red[0] = w;
    }
    __syncthreads();
    float r = red[0];
    __syncthreads();
    return r;
}

DEV int pix_of(int k, int l) {
    int p = (k == 2 || k == 3 || k == 6 || k == 7) ? (255 - l) : l;
    switch (k) {
        case 0: case 2: return p;
        case 1: case 3: { int w = p >> 4, h = p & 15; return h * 16 + w; }
        case 4: case 6: { int wp = p >> 4, h = p & 15; int w = (h + wp) & 15; return h * 16 + w; }
        default:        { int wp = p >> 4, h = p & 15; int w = (wp - h) & 15; return h * 16 + w; }
    }
}

DEV void split_h(float v, __half& h, __half& l) {
    h = __float2half(v);
    l = __float2half(v - __half2float(h));
}

DEV unsigned smem_u32(const void* p) {
    unsigned a;
    asm("{ .reg .u64 t; cvta.to.shared.u64 t, %1; cvt.u32.u64 %0, t; }" : "=r"(a) : "l"(p));
    return a;
}

DEV void cp16(unsigned dst, const void* src) {
    asm volatile("cp.async.cg.shared.global [%0], [%1], 16;" :: "r"(dst), "l"(src));
}
DEV void cp_commit() { asm volatile("cp.async.commit_group;" ::: "memory"); }
template <int N> DEV void cp_wait() { asm volatile("cp.async.wait_group %0;" :: "n"(N) : "memory"); }

DEV void ldmx4(unsigned* r, unsigned addr) {
    asm volatile("ldmatrix.sync.aligned.m8n8.x4.shared.b16 {%0,%1,%2,%3}, [%4];"
                 : "=r"(r[0]), "=r"(r[1]), "=r"(r[2]), "=r"(r[3]) : "r"(addr));
}
DEV void mma_f16(float* d, const unsigned* a, const unsigned* b) {
    asm volatile(
        "mma.sync.aligned.m16n8k16.row.col.f32.f16.f16.f32 "
        "{%0,%1,%2,%3}, {%4,%5,%6,%7}, {%8,%9}, {%0,%1,%2,%3};"
        : "+f"(d[0]), "+f"(d[1]), "+f"(d[2]), "+f"(d[3])
        : "r"(a[0]), "r"(a[1]), "r"(a[2]), "r"(a[3]), "r"(b[0]), "r"(b[1]));
}

// ---------------- stage 1: pyramid pooling ----------------
__global__ void k_pool(const float* __restrict__ x) {
    __shared__ float sx[256];
    int b = blockIdx.x / 512, c = blockIdx.x % 512;
    const float* xp = x + (b * 512 + c) * 256;
    for (int i = threadIdx.x; i < 256; i += blockDim.x) sx[i] = xp[i];
    __syncthreads();
    int t = threadIdx.x;
    if (t < 275) {
        int s, idx;
        if (t < 25)       { s = 5;  idx = t; }
        else if (t < 106) { s = 9;  idx = t - 25; }
        else              { s = 13; idx = t - 106; }
        int i = idx / s, j = idx % s;
        int r0 = i * 16 / s, r1 = ((i + 1) * 16 + s - 1) / s;
        int c0 = j * 16 / s, c1 = ((j + 1) * 16 + s - 1) / s;
        float sum = 0.f;
        for (int r = r0; r < r1; r++)
            for (int cc = c0; cc < c1; cc++) sum += sx[r * 16 + cc];
        g_pool[(b * 512 + c) * 275 + t] = sum / (float)((r1 - r0) * (c1 - c0));
    }
}

// ---------------- CBR as tiled GEMM ----------------------------------------
__global__ void __launch_bounds__(256)
k_cbr_gemm(const float* __restrict__ x, int useX, int off, int posCnt, int scale,
           const float* __restrict__ pw, const float* __restrict__ bn_g,
           const float* __restrict__ bn_b, int tilesPerB) {
    int b = blockIdx.x / tilesPerB, tile = blockIdx.x % tilesPerB;
    int pos0 = tile * 32;
    if (pos0 >= posCnt) return;
    __shared__ float ws[128][33];
    __shared__ float ps[32][33];
    int tid = threadIdx.x, lane = tid & 31, warp = tid >> 5;
    int tx = tid & 7, ty = tid >> 3;
    int ldS = useX ? 256 : 275;
    const float* src = useX ? x : (const float*)g_pool;
    float acc[4][4];
#pragma unroll
    for (int i = 0; i < 4; i++)
#pragma unroll
        for (int j = 0; j < 4; j++) acc[i][j] = 0.f;

    for (int k0 = 0; k0 < 512; k0 += 32) {
#pragma unroll
        for (int i = 0; i < 16; i++) {
            int o = warp * 16 + i;
            ws[o][lane] = pw[(long)(scale * 128 + o) * 512 + k0 + lane];
        }
#pragma unroll
        for (int i = 0; i < 4; i++) {
            int kc = warp * 4 + i, c = k0 + kc;
            int p = pos0 + lane;
            ps[kc][lane] = (p < posCnt) ? src[((long)b * 512 + c) * ldS + off + p] : 0.f;
        }
        __syncthreads();
#pragma unroll
        for (int kc = 0; kc < 32; kc++) {
            float a0 = ws[ty * 4 + 0][kc], a1 = ws[ty * 4 + 1][kc];
            float a2 = ws[ty * 4 + 2][kc], a3 = ws[ty * 4 + 3][kc];
            float p0 = ps[kc][tx * 4 + 0], p1 = ps[kc][tx * 4 + 1];
            float p2 = ps[kc][tx * 4 + 2], p3 = ps[kc][tx * 4 + 3];
            acc[0][0] += a0 * p0; acc[0][1] += a0 * p1; acc[0][2] += a0 * p2; acc[0][3] += a0 * p3;
            acc[1][0] += a1 * p0; acc[1][1] += a1 * p1; acc[1][2] += a1 * p2; acc[1][3] += a1 * p3;
            acc[2][0] += a2 * p0; acc[2][1] += a2 * p1; acc[2][2] += a2 * p2; acc[2][3] += a2 * p3;
            acc[3][0] += a3 * p0; acc[3][1] += a3 * p1; acc[3][2] += a3 * p2; acc[3][3] += a3 * p3;
        }
        __syncthreads();
    }
    float gsc = rsqrtf(1.f + 1e-5f);
#pragma unroll
    for (int i = 0; i < 4; i++) {
        int o = ty * 4 + i;
        float g = bn_g[scale * 128 + o] * gsc;
        float bb = bn_b[scale * 128 + o];
#pragma unroll
        for (int j = 0; j < 4; j++) {
            int p = pos0 + tx * 4 + j;
            if (p < posCnt) {
                float v = fminf(fmaxf(acc[i][j] * g + bb, 0.f), 6.f);
                if (useX) g_p0map[((long)b * 128 + o) * 256 + p] = v;
                else      g_cbr [((long)b * 128 + o) * 275 + off + p] = v;
            }
        }
    }
}

__global__ void k_p0_reduce() {
    int b = blockIdx.x >> 7, o = blockIdx.x & 127;
    __shared__ float red[256];
    int p = threadIdx.x;
    red[p] = g_p0map[((long)b * 128 + o) * 256 + p];
    __syncthreads();
    for (int st = 128; st > 0; st >>= 1) { if (p < st) red[p] += red[p + st]; __syncthreads(); }
    if (p == 0) g_p0[b * 128 + o] = red[0] * (1.f / 256.f);
}

__global__ void k_assemble(const float* __restrict__ x) {
    int b = blockIdx.x / 256, pix = blockIdx.x % 256;
    int h = pix / 16, w = pix % 16;
    float* out = g_xcT + (b * 256 + pix) * 1024;
    for (int i = 0; i < 4; i++) {
        int c = threadIdx.x + i * 256;
        float v;
        if (c < 128) {
            v = g_p0[b * 128 + c];
        } else if (c < 512) {
            int sc = (c - 128) / 128, o = (c - 128) % 128;
            int s   = sc == 0 ? 5 : (sc == 1 ? 9 : 13);
            int off = sc == 0 ? 0 : (sc == 1 ? 25 : 106);
            float fy = (h + 0.5f) * s * (1.f / 16.f) - 0.5f;
            float fx = (w + 0.5f) * s * (1.f / 16.f) - 0.5f;
            int y0 = (int)floorf(fy), x0 = (int)floorf(fx);
            float wy = fy - y0, wx = fx - x0;
            int y1 = min(y0 + 1, s - 1), x1 = min(x0 + 1, s - 1);
            y0 = max(y0, 0); x0 = max(x0, 0);
            const float* base = g_cbr + (b * 128 + o) * 275 + off;
            float v00 = base[y0 * s + x0], v01 = base[y0 * s + x1];
            float v10 = base[y1 * s + x0], v11 = base[y1 * s + x1];
            v = v00 * (1 - wy) * (1 - wx) + v01 * (1 - wy) * wx
              + v10 * wy * (1 - wx) + v11 * wy * wx;
        } else {
            v = x[(b * 512 + (c - 512)) * 256 + pix];
        }
        out[c] = v;
    }
}

// ---------------- stage 2: gate weights (softmax + top4) ----------------
__global__ void k_gate_weights(const float* __restrict__ gate_w) {
    __shared__ float sm[1024];
    __shared__ float slog[8];
    int b = blockIdx.x, t = threadIdx.x;
    float s = 0.f;
    const float* base = g_xcT + b * 256 * 1024;
    for (int p = 0; p < 256; p++) s += base[p * 1024 + t];
    sm[t] = s * (1.f / 256.f);
    __syncthreads();
    if (t < 256) {
        int k = t / 32, lane = t % 32;
        float acc = 0.f;
        for (int c = lane; c < 1024; c += 32) acc += sm[c] * gate_w[k * 1024 + c];
#pragma unroll
        for (int o = 16; o > 0; o >>= 1) acc += __shfl_down_sync(0xffffffffu, acc, o);
        if (lane == 0) slog[k] = acc;
    }
    __syncthreads();
    if (t == 0) {
        float mx = -1e30f;
        for (int k = 0; k < 8; k++) mx = fmaxf(mx, slog[k]);
        float e[8], se = 0.f;
        for (int k = 0; k < 8; k++) { e[k] = expf(slog[k] - mx); se += e[k]; }
        float sc[8];
        for (int k = 0; k < 8; k++) sc[k] = e[k] / se;
        float gwv[8];
        bool used[8];
        for (int k = 0; k < 8; k++) { gwv[k] = 0.f; used[k] = false; }
        for (int r = 0; r < 4; r++) {
            int bi = -1; float bv = -1e30f;
            for (int k = 0; k < 8; k++)
                if (!used[k] && sc[k] > bv) { bv = sc[k]; bi = k; }
            used[bi] = true; gwv[bi] = bv;
        }
        for (int k = 0; k < 8; k++) g_gw[b * 8 + k] = gwv[k];
    }
}

// ---------------- stage 3: cross-scan + fd_gate -> xg (fp16) ---------------
__global__ void k_fdgate(const float* __restrict__ ln_g, const float* __restrict__ ln_b,
                         const float* __restrict__ fd_scale) {
    int z = blockIdx.x;
    int l = z & 255, k = (z >> 8) & 7, b = z >> 11;
    if (g_gw[b * 8 + k] == 0.f) return;
    int pix = pix_of(k, l);
    int pixp = (l > 0) ? pix_of(k, l - 1) : -1;
    const float* cur = g_xcT + (b * 256 + pix) * 1024;
    const float* prv = (pixp >= 0) ? g_xcT + (b * 256 + pixp) * 1024 : nullptr;
    __shared__ float red[32];
    int t = threadIdx.x;
    float xv[4], dv[4];
    float s1 = 0.f, s2 = 0.f;
#pragma unroll
    for (int i = 0; i < 4; i++) {
        int c = t + i * 256;
        xv[i] = cur[c];
        float pvv = prv ? prv[c] : 0.f;
        dv[i] = xv[i] - pvv;
        s1 += dv[i];
        s2 += dv[i] * dv[i];
    }
    float S1 = block_sum(s1, red);
    float S2 = block_sum(s2, red);
    float mu = S1 * (1.f / 1024.f);
    float var = S2 * (1.f / 1024.f) - mu * mu;
    float rstd = rsqrtf(var + 1e-5f);
    float s3 = 0.f;
#pragma unroll
    for (int i = 0; i < 4; i++) {
        int c = t + i * 256;
        float dn = (dv[i] - mu) * rstd * ln_g[c] + ln_b[c];
        s3 += dn * dn;
    }
    float S3 = block_sum(s3, red);
    float nd = sqrtf(S3) * fd_scale[0];
    float gate = 0.2f + 0.8f * tanhf(fabsf(nd));
    long rowoff = ((long)(b * 8 + k) * 256 + l) * 1024;
#pragma unroll
    for (int i = 0; i < 4; i++) {
        int c = t + i * 256;
        g_xgf[rowoff + c] = __float2half(xv[i] * gate);
    }
}

// ---------------- weight conversions ----------------------------------------
__global__ void k_split4(const float4* __restrict__ src, int which, int n4) {
    int i = blockIdx.x * 256 + threadIdx.x;
    if (i >= n4) return;
    float4 v = src[i];
    __half2 a = __floats2half2_rn(v.x, v.y);
    __half2 b = __floats2half2_rn(v.z, v.w);
    __half2* dst = (which == 0) ? (__half2*)g_iwf : (__half2*)g_owf;
    dst[i * 2]     = a;
    dst[i * 2 + 1] = b;
}
__global__ void k_split(const float* __restrict__ src, int which, int n) {
    int i = blockIdx.x * 256 + threadIdx.x;
    if (i >= n) return;
    float v = src[i];
    if (which == 2) { __half h, l; split_h(v, h, l); g_xpwh[i] = h; g_xpwl[i] = l; }
    else            { __half h, l; split_h(v, h, l); g_dtwh[i] = h; g_dtwl[i] = l; }
}

// ---------------- fp16 HMMA GEMM (K-chunk 64, 3-stage ring, fp16 out) -------
#define RS144 144               // row stride bytes (64 halves + 8 pad)
#define MATB64 (128 * RS144)    // 18432 bytes per matrix
#define G_OFF_A 0
#define G_OFF_B (MATB64)
#define G_STAGE (2 * MATB64)    // 36864
#define G_NSTAGE 3
#define G_SMEM (G_NSTAGE * G_STAGE)  // 110592

DEV void issue64(unsigned sbs, const __half* __restrict__ A, const __half* __restrict__ Bm,
                 int K, int k0, int tid) {
#pragma unroll
    for (int i = 0; i < 4; i++) {
        int idx = tid + i * 256;
        int row = idx >> 3, g = idx & 7;
        cp16(sbs + G_OFF_A + row * RS144 + g * 16, A + (long)row * K + k0 + g * 8);
        cp16(sbs + G_OFF_B + row * RS144 + g * 16, Bm + (long)row * K + k0 + g * 8);
    }
    cp_commit();
}

// sel: 0 -> A=g_xgf (K=1024), B=g_iwf (N=4096), C=g_xzf
//      1 -> A=g_y2f (K=2048), B=g_owf (N=1024), C=g_ysf
__global__ void __launch_bounds__(256)
k_gemm_h(int sel, int N, int K) {
    int zi = blockIdx.z;
    int kk = zi >> 3, b = zi & 7;
    int z = b * 8 + kk;
    if (g_gw[z] == 0.f) return;

    const __half *A, *Bm;
    __half* C;
    if (sel == 0) {
        A  = g_xgf + (long)z * 256 * 1024;
        Bm = g_iwf + (long)kk * 4096 * 1024;
        C  = g_xzf + (long)z * 256 * 4096;
    } else {
        A  = g_y2f + (long)z * 256 * 2048;
        Bm = g_owf + (long)kk * 1024 * 2048;
        C  = g_ysf + (long)z * 256 * 1024;
    }

    int bm = blockIdx.y * 128, bn = blockIdx.x * 128;
    A  += (long)bm * K;
    Bm += (long)bn * K;

    extern __shared__ char dsm[];
    unsigned sb0 = smem_u32(dsm);
    int tid = threadIdx.x;
    int lane = tid & 31, warp = tid >> 5;
    int wm = (warp & 1) * 64, wn = (warp >> 1) * 32;
    int mi = lane >> 3, lr = lane & 7;
    int arow = (mi & 1) * 8 + lr;
    int akb  = (mi >> 1) * 16;
    int brow = (mi >> 1) * 8 + lr;
    int bkb  = (mi & 1) * 16;

    float acc[4][4][4];
#pragma unroll
    for (int i = 0; i < 4; i++)
#pragma unroll
        for (int j = 0; j < 4; j++)
#pragma unroll
            for (int r = 0; r < 4; r++) acc[i][j][r] = 0.f;

    int nk = K >> 6;

    issue64(sb0 + 0 * G_STAGE, A, Bm, K, 0, tid);
    issue64(sb0 + 1 * G_STAGE, A, Bm, K, 64, tid);
    cp_commit();   // empty pad group

    for (int j = 0; j < nk; j++) {
        cp_wait<2>();
        __syncthreads();
        if (j + 2 < nk) issue64(sb0 + ((j + 2) % 3) * G_STAGE, A, Bm, K, (j + 2) << 6, tid);
        else            cp_commit();
        unsigned sbs = sb0 + (j % 3) * G_STAGE;
#pragma unroll
        for (int ks = 0; ks < 4; ks++) {
            unsigned kb = ks * 32;
            unsigned ah[4][4];
#pragma unroll
            for (int mf = 0; mf < 4; mf++) {
                unsigned ro = (wm + mf * 16 + arow) * RS144 + kb + akb;
                ldmx4(ah[mf], sbs + G_OFF_A + ro);
            }
            unsigned bh[2][4];
#pragma unroll
            for (int p = 0; p < 2; p++) {
                unsigned ro = (wn + p * 16 + brow) * RS144 + kb + bkb;
                ldmx4(bh[p], sbs + G_OFF_B + ro);
            }
#pragma unroll
            for (int mf = 0; mf < 4; mf++)
#pragma unroll
                for (int nf = 0; nf < 4; nf++) {
                    const unsigned* bhp = &bh[nf >> 1][(nf & 1) * 2];
                    mma_f16(acc[mf][nf], ah[mf], bhp);
                }
        }
    }

    int g = lane >> 2, tI = lane & 3;
#pragma unroll
    for (int mf = 0; mf < 4; mf++) {
        int r0 = bm + wm + mf * 16 + g;
#pragma unroll
        for (int nf = 0; nf < 4; nf++) {
            int col = bn + wn + nf * 8 + tI * 2;
            *(__half2*)(C + (long)r0 * N + col)       = __floats2half2_rn(acc[mf][nf][0], acc[mf][nf][1]);
            *(__half2*)(C + (long)(r0 + 8) * N + col) = __floats2half2_rn(acc[mf][nf][2], acc[mf][nf][3]);
        }
    }
}

// ---------------- HMMA x_dbl GEMM (3-term hi/lo split) ----------------------
#define RS80 80
#define MAT_B (128 * RS80)
#define X_OFF_AH 0
#define X_OFF_AL (MAT_B)
#define X_OFF_BH (2 * MAT_B)
#define X_OFF_BL (3 * MAT_B)
#define X_STAGE (4 * MAT_B)     // 40960
#define X_GSMEM (2 * X_STAGE)   // 81920

__global__ void __launch_bounds__(256)
k_gemm_xdbl_h() {
    int z = blockIdx.y;
    int kk = z & 7;
    if (g_gw[z] == 0.f) return;
    const int K = 2048;
    const __half* Ah = g_uh + (long)z * 256 * 2048;
    const __half* Al = g_ul + (long)z * 256 * 2048;
    const __half* Bh = g_xpwh + (long)kk * 96 * 2048;
    const __half* Bl = g_xpwl + (long)kk * 96 * 2048;
    float* C = g_xdbl + (long)z * 256 * 96;
    __half* Dh = g_xdh + (long)z * 256 * 64;
    __half* Dl = g_xdl + (long)z * 256 * 64;

    int bm = blockIdx.x * 128;
    Ah += (long)bm * K; Al += (long)bm * K;

    extern __shared__ char dsm[];
    unsigned sb0 = smem_u32(dsm);
    int tid = threadIdx.x;
    int lane = tid & 31, warp = tid >> 5;
    int wm = (warp & 1) * 64, wn = (warp >> 1) * 24;
    int mi = lane >> 3, lr = lane & 7;
    int arow = (mi & 1) * 8 + lr;
    int akb  = (mi >> 1) * 16;
    int brow = (mi >> 1) * 8 + lr;
    int bkb  = (mi & 1) * 16;

    float acc[4][3][4];
#pragma unroll
    for (int i = 0; i < 4; i++)
#pragma unroll
        for (int j = 0; j < 3; j++)
#pragma unroll
            for (int r = 0; r < 4; r++) acc[i][j][r] = 0.f;

    int ci0 = tid * 2;
    int row0 = ci0 >> 2, kc0 = (ci0 & 3);
    int row1 = (ci0 + 1) >> 2, kc1 = ((ci0 + 1) & 3);
    int rb0 = row0 < 96 ? row0 : 95;
    int rb1 = row1 < 96 ? row1 : 95;

#define XISSUE(J, BUF)                                                                       \
    {                                                                                        \
        int k0 = (J) << 5;                                                                   \
        unsigned sbs = sb0 + (BUF) * X_STAGE;                                                \
        cp16(sbs + X_OFF_AH + row0 * RS80 + kc0 * 16, Ah + (long)row0 * K + k0 + kc0 * 8);   \
        cp16(sbs + X_OFF_AH + row1 * RS80 + kc1 * 16, Ah + (long)row1 * K + k0 + kc1 * 8);   \
        cp16(sbs + X_OFF_AL + row0 * RS80 + kc0 * 16, Al + (long)row0 * K + k0 + kc0 * 8);   \
        cp16(sbs + X_OFF_AL + row1 * RS80 + kc1 * 16, Al + (long)row1 * K + k0 + kc1 * 8);   \
        cp16(sbs + X_OFF_BH + row0 * RS80 + kc0 * 16, Bh + (long)rb0 * K + k0 + kc0 * 8);    \
        cp16(sbs + X_OFF_BH + row1 * RS80 + kc1 * 16, Bh + (long)rb1 * K + k0 + kc1 * 8);    \
        cp16(sbs + X_OFF_BL + row0 * RS80 + kc0 * 16, Bl + (long)rb0 * K + k0 + kc0 * 8);    \
        cp16(sbs + X_OFF_BL + row1 * RS80 + kc1 * 16, Bl + (long)rb1 * K + k0 + kc1 * 8);    \
        cp_commit();                                                                         \
    }

    const int nk = 64;
    XISSUE(0, 0);
    for (int j = 0; j < nk; j++) {
        if (j + 1 < nk) { XISSUE(j + 1, (j + 1) & 1); cp_wait<1>(); }
        else            { cp_wait<0>(); }
        __syncthreads();
        unsigned sbs = sb0 + (j & 1) * X_STAGE;
#pragma unroll
        for (int ks = 0; ks < 2; ks++) {
            unsigned kb = ks * 32;
            unsigned ah[4][4], al[4][4];
#pragma unroll
            for (int mf = 0; mf < 4; mf++) {
                unsigned ro = (wm + mf * 16 + arow) * RS80 + kb + akb;
                ldmx4(ah[mf], sbs + X_OFF_AH + ro);
                ldmx4(al[mf], sbs + X_OFF_AL + ro);
            }
            unsigned bh[2][4], bl[2][4];
#pragma unroll
            for (int p = 0; p < 2; p++) {
                unsigned ro = (wn + p * 16 + brow) * RS80 + kb + bkb;
                ldmx4(bh[p], sbs + X_OFF_BH + ro);
                ldmx4(bl[p], sbs + X_OFF_BL + ro);
            }
#pragma unroll
            for (int mf = 0; mf < 4; mf++)
#pragma unroll
                for (int nf = 0; nf < 3; nf++) {
                    const unsigned* bhp = &bh[nf >> 1][(nf & 1) * 2];
                    const unsigned* blp = &bl[nf >> 1][(nf & 1) * 2];
                    mma_f16(acc[mf][nf], ah[mf], bhp);
                    mma_f16(acc[mf][nf], ah[mf], blp);
                    mma_f16(acc[mf][nf], al[mf], bhp);
                }
        }
        __syncthreads();
    }

    int g = lane >> 2, tI = lane & 3;
#pragma unroll
    for (int mf = 0; mf < 4; mf++) {
        int r0 = bm + wm + mf * 16 + g;
#pragma unroll
        for (int nf = 0; nf < 3; nf++) {
            int col = wn + nf * 8 + tI * 2;
#pragma unroll
            for (int half = 0; half < 2; half++) {
                int r = r0 + half * 8;
                float v0 = acc[mf][nf][half * 2 + 0];
                float v1 = acc[mf][nf][half * 2 + 1];
                C[(long)r * 96 + col]     = v0;
                C[(long)r * 96 + col + 1] = v1;
                if (col < 64) {
                    __half h0, l0, h1, l1;
                    split_h(v0, h0, l0);
                    split_h(v1, h1, l1);
                    Dh[(long)r * 64 + col]     = h0;
                    Dl[(long)r * 64 + col]     = l0;
                    Dh[(long)r * 64 + col + 1] = h1;
                    Dl[(long)r * 64 + col + 1] = l1;
                }
            }
        }
    }
}

// ---------------- HMMA dt GEMM (3-term hi/lo split, K=64, fp16 out) ---------
__global__ void __launch_bounds__(256)
k_gemm_dt_h(const float* __restrict__ bias) {
    int z = blockIdx.z;
    int kk = z & 7;
    if (g_gw[z] == 0.f) return;
    const int K = 64, N = 2048;
    const __half* Ah = g_xdh + (long)z * 256 * 64;
    const __half* Al = g_xdl + (long)z * 256 * 64;
    const __half* Bh = g_dtwh + (long)kk * 2048 * 64;
    const __half* Bl = g_dtwl + (long)kk * 2048 * 64;
    __half* C = g_dtf + (long)z * 256 * 2048;

    int bm = blockIdx.y * 128, bn = blockIdx.x * 128;
    Ah += (long)bm * K; Al += (long)bm * K;
    Bh += (long)bn * K; Bl += (long)bn * K;

    extern __shared__ char dsm[];
    unsigned sb0 = smem_u32(dsm);
    int tid = threadIdx.x;
    int lane = tid & 31, warp = tid >> 5;
    int wm = (warp & 1) * 64, wn = (warp >> 1) * 32;
    int mi = lane >> 3, lr = lane & 7;
    int arow = (mi & 1) * 8 + lr;
    int akb  = (mi >> 1) * 16;
    int brow = (mi >> 1) * 8 + lr;
    int bkb  = (mi & 1) * 16;

    float acc[4][4][4];
#pragma unroll
    for (int i = 0; i < 4; i++)
#pragma unroll
        for (int j = 0; j < 4; j++)
#pragma unroll
            for (int r = 0; r < 4; r++) acc[i][j][r] = 0.f;

    int ci0 = tid * 2;
    int row0 = ci0 >> 2, kc0 = (ci0 & 3);
    int row1 = (ci0 + 1) >> 2, kc1 = ((ci0 + 1) & 3);

#define DISSUE(J, BUF)                                                                       \
    {                                                                                        \
        int k0 = (J) << 5;                                                                   \
        unsigned sbs = sb0 + (BUF) * X_STAGE;                                                \
        cp16(sbs + X_OFF_AH + row0 * RS80 + kc0 * 16, Ah + (long)row0 * K + k0 + kc0 * 8);   \
        cp16(sbs + X_OFF_AH + row1 * RS80 + kc1 * 16, Ah + (long)row1 * K + k0 + kc1 * 8);   \
        cp16(sbs + X_OFF_AL + row0 * RS80 + kc0 * 16, Al + (long)row0 * K + k0 + kc0 * 8);   \
        cp16(sbs + X_OFF_AL + row1 * RS80 + kc1 * 16, Al + (long)row1 * K + k0 + kc1 * 8);   \
        cp16(sbs + X_OFF_BH + row0 * RS80 + kc0 * 16, Bh + (long)row0 * K + k0 + kc0 * 8);   \
        cp16(sbs + X_OFF_BH + row1 * RS80 + kc1 * 16, Bh + (long)row1 * K + k0 + kc1 * 8);   \
        cp16(sbs + X_OFF_BL + row0 * RS80 + kc0 * 16, Bl + (long)row0 * K + k0 + kc0 * 8);   \
        cp16(sbs + X_OFF_BL + row1 * RS80 + kc1 * 16, Bl + (long)row1 * K + k0 + kc1 * 8);   \
        cp_commit();                                                                         \
    }

    DISSUE(0, 0);
    DISSUE(1, 1);
    cp_wait<0>();
    __syncthreads();

#pragma unroll
    for (int j = 0; j < 2; j++) {
        unsigned sbs = sb0 + j * X_STAGE;
#pragma unroll
        for (int ks = 0; ks < 2; ks++) {
            unsigned kb = ks * 32;
            unsigned ah[4][4], al[4][4];
#pragma unroll
            for (int mf = 0; mf < 4; mf++) {
                unsigned ro = (wm + mf * 16 + arow) * RS80 + kb + akb;
                ldmx4(ah[mf], sbs + X_OFF_AH + ro);
                ldmx4(al[mf], sbs + X_OFF_AL + ro);
            }
            unsigned bh[2][4], bl[2][4];
#pragma unroll
            for (int p = 0; p < 2; p++) {
                unsigned ro = (wn + p * 16 + brow) * RS80 + kb + bkb;
                ldmx4(bh[p], sbs + X_OFF_BH + ro);
                ldmx4(bl[p], sbs + X_OFF_BL + ro);
            }
#pragma unroll
            for (int mf = 0; mf < 4; mf++)
#pragma unroll
                for (int nf = 0; nf < 4; nf++) {
                    const unsigned* bhp = &bh[nf >> 1][(nf & 1) * 2];
                    const unsigned* blp = &bl[nf >> 1][(nf & 1) * 2];
                    mma_f16(acc[mf][nf], ah[mf], bhp);
                    mma_f16(acc[mf][nf], ah[mf], blp);
                    mma_f16(acc[mf][nf], al[mf], bhp);
                }
        }
    }

    int g = lane >> 2, tI = lane & 3;
#pragma unroll
    for (int mf = 0; mf < 4; mf++) {
        int r0 = bm + wm + mf * 16 + g;
#pragma unroll
        for (int nf = 0; nf < 4; nf++) {
            int col = bn + wn + nf * 8 + tI * 2;
            float b0 = bias[kk * N + col], b1 = bias[kk * N + col + 1];
#pragma unroll
            for (int half = 0; half < 2; half++) {
                int r = r0 + half * 8;
                float v0 = acc[mf][nf][half * 2 + 0] + b0;
                float v1 = acc[mf][nf][half * 2 + 1] + b1;
                v0 = (v0 > 20.f) ? v0 : log1pf(__expf(v0));
                v1 = (v1 > 20.f) ? v1 : log1pf(__expf(v1));
                C[(long)r * N + col]     = __float2half(v0);
                C[(long)r * N + col + 1] = __float2half(v1);
            }
        }
    }
}

// ---------------- depthwise causal conv (l-parallel, fp16 in) ---------------
__global__ void k_conv(const float* __restrict__ cw, const float* __restrict__ cb) {
    int gb = blockIdx.x;
    int l = gb & 255, z = gb >> 8;
    int k = z & 7;
    if (g_gw[z] == 0.f) return;
    const __half* xzb = g_xzf + (long)z * 256 * 4096;
    long ubase = ((long)z * 256 + l) * 2048;
#pragma unroll
    for (int i = 0; i < 8; i++) {
        int d = threadIdx.x + i * 256;
        float4 w4 = ((const float4*)cw)[k * 2048 + d];
        float acc = cb[k * 2048 + d];
        float wv[4] = {w4.x, w4.y, w4.z, w4.w};
#pragma unroll
        for (int j = 0; j < 4; j++) {
            int lp = l - 3 + j;
            if (lp >= 0) acc += wv[j] * __half2float(xzb[(long)lp * 4096 + d]);
        }
        float u = acc / (1.f + __expf(-acc));  // silu
        __half h, lo;
        split_h(u, h, lo);
        g_uh[ubase + d] = h;
        g_ul[ubase + d] = lo;
    }
}

// ---------------- selective scan -> y2 fp16 ---------------------------------
__global__ void k_scan(const float* __restrict__ A_log, const float* __restrict__ D_p) {
    __shared__ float sbc[256 * 32];
    int gb = blockIdx.x;
    int z = gb >> 3, dblk = gb & 7;
    int k = z & 7;
    if (g_gw[z] == 0.f) return;
    for (int idx = threadIdx.x; idx < 8192; idx += 256)
        sbc[idx] = g_xdbl[((long)z * 256 + (idx >> 5)) * 96 + 64 + (idx & 31)];
    __syncthreads();
    int d = dblk * 256 + threadIdx.x;
    float a[16];
#pragma unroll
    for (int s = 0; s < 16; s++) a[s] = -__expf(A_log[(long)(k * 2048 + d) * 16 + s]);
    bool fast = true;
#pragma unroll
    for (int s = 0; s < 16; s++) {
        float r = a[s] / a[0];
        if (fabsf(r - (float)(s + 1)) > 1e-4f) fast = false;
    }
    float dp = D_p[k * 2048 + d];
    float h[16];
#pragma unroll
    for (int s = 0; s < 16; s++) h[s] = 0.f;
    const __half* dtb = g_dtf + (long)z * 256 * 2048 + d;
    const __half* uhb = g_uh + (long)z * 256 * 2048 + d;
    const __half* ulb = g_ul + (long)z * 256 * 2048 + d;
    const __half* zb  = g_xzf + (long)z * 256 * 4096 + 2048 + d;
    long ybase = (long)z * 256 * 2048 + d;
    for (int l = 0; l < 256; l++) {
        float dt = __half2float(dtb[(long)l * 2048]);
        float uu = __half2float(uhb[(long)l * 2048]) + __half2float(ulb[(long)l * 2048]);
        float zz = __half2float(zb[(long)l * 4096]);
        float dtu = dt * uu;
        float acc = 0.f;
        const float* bc = &sbc[l * 32];
        if (fast) {
            float e = __expf(dt * a[0]);
            float p = 1.f;
#pragma unroll
            for (int s = 0; s < 16; s++) {
                p *= e;
                h[s] = p * h[s] + dtu * bc[s];
                acc += h[s] * bc[16 + s];
            }
        } else {
#pragma unroll
            for (int s = 0; s < 16; s++) {
                float e = __expf(dt * a[s]);
                h[s] = e * h[s] + dtu * bc[s];
                acc += h[s] * bc[16 + s];
            }
        }
        float y = acc + uu * dp;
        y *= zz / (1.f + __expf(-zz));  // * silu(z)
        g_y2f[ybase + (long)l * 2048] = __float2half(y);
    }
}

// ---------------- cross-merge (gather + gated sum, fp16 in) -----------------
__global__ void k_merge(float* __restrict__ out) {
    int t = blockIdx.x * 256 + threadIdx.x;
    int pix = t & 255, c = (t >> 8) & 1023, b = t >> 18;
    int h = pix >> 4, w = pix & 15;
    int l0 = pix;
    int l1 = w * 16 + h;
    int ld = ((w - h) & 15) * 16 + h;
    int la = ((w + h) & 15) * 16 + h;
    int pos[8] = {l0, l1, 255 - l0, 255 - l1, ld, la, 255 - ld, 255 - la};
    float acc = 0.f;
#pragma unroll
    for (int k = 0; k < 8; k++) {
        float g = g_gw[b * 8 + k];
        if (g != 0.f)
            acc += g * __half2float(g_ysf[((long)(b * 8 + k) * 256 + pos[k]) * 1024 + c]);
    }
    out[t] = acc;
}

// ---------------- launch ----------------
extern "C" void kernel_launch(void* const* d_in, const int* in_sizes, int n_in,
                              void* d_out, int out_size) {
    const float* x        = (const float*)d_in[0];
    const float* pw       = (const float*)d_in[1];
    const float* bn_g     = (const float*)d_in[2];
    const float* bn_b     = (const float*)d_in[3];
    const float* gate_w   = (const float*)d_in[4];
    const float* ln_g     = (const float*)d_in[5];
    const float* ln_b     = (const float*)d_in[6];
    const float* fd_scale = (const float*)d_in[7];
    const float* in_w     = (const float*)d_in[8];
    const float* cw       = (const float*)d_in[9];
    const float* cb       = (const float*)d_in[10];
    const float* xp_w     = (const float*)d_in[11];
    const float* dtp_w    = (const float*)d_in[12];
    const float* dtp_b    = (const float*)d_in[13];
    const float* A_log    = (const float*)d_in[14];
    const float* D_p      = (const float*)d_in[15];
    const float* out_w    = (const float*)d_in[16];
    float* out = (float*)d_out;

    cudaFuncSetAttribute(k_gemm_h, cudaFuncAttributeMaxDynamicSharedMemorySize, G_SMEM);
    cudaFuncSetAttribute(k_gemm_xdbl_h, cudaFuncAttributeMaxDynamicSharedMemorySize, X_GSMEM);
    cudaFuncSetAttribute(k_gemm_dt_h, cudaFuncAttributeMaxDynamicSharedMemorySize, X_GSMEM);

    // weight conversions (deterministic, every call)
    {
        int n1 = 8 * 4096 * 1024, n2 = 8 * 1024 * 2048;
        int n3 = 8 * 96 * 2048,   n4 = 8 * 2048 * 64;
        k_split4<<<(n1 / 4) / 256, 256>>>((const float4*)in_w, 0, n1 / 4);
        k_split4<<<(n2 / 4) / 256, 256>>>((const float4*)out_w, 1, n2 / 4);
        k_split<<<(n3 + 255) / 256, 256>>>(xp_w, 2, n3);
        k_split<<<(n4 + 255) / 256, 256>>>(dtp_w, 3, n4);
    }

    k_pool<<<8 * 512, 288>>>(x);
    k_cbr_gemm<<<8 * 8, 256>>>(x, 1, 0,   256, 0, pw, bn_g, bn_b, 8);   // p0 map
    k_cbr_gemm<<<8 * 1, 256>>>(x, 0, 0,    25, 1, pw, bn_g, bn_b, 1);   // s=5
    k_cbr_gemm<<<8 * 3, 256>>>(x, 0, 25,   81, 2, pw, bn_g, bn_b, 3);   // s=9
    k_cbr_gemm<<<8 * 6, 256>>>(x, 0, 106, 169, 3, pw, bn_g, bn_b, 6);   // s=13
    k_p0_reduce<<<8 * 128, 256>>>();
    k_assemble<<<8 * 256, 256>>>(x);
    k_gate_weights<<<8, 1024>>>(gate_w);
    k_fdgate<<<8 * 8 * 256, 256>>>(ln_g, ln_b, fd_scale);

    // in_proj (fp16 HMMA, K-chunk 64, fp16 out)
    { dim3 g(32, 2, 64); k_gemm_h<<<g, 256, G_SMEM>>>(0, 4096, 1024); }
    // depthwise conv + silu -> u hi/lo (l-parallel, fp16 in)
    k_conv<<<64 * 256, 256>>>(cw, cb);
    // x_dbl (HMMA 3-term)
    { dim3 g(2, 64); k_gemm_xdbl_h<<<g, 256, X_GSMEM>>>(); }
    // dt projection + softplus (HMMA 3-term, fp16 out)
    { dim3 g(16, 2, 64); k_gemm_dt_h<<<g, 256, X_GSMEM>>>(dtp_b); }
    // selective scan
    k_scan<<<64 * 8, 256>>>(A_log, D_p);
    // out_proj (fp16 HMMA, K-chunk 64, fp16 out)
    { dim3 g(8, 2, 64); k_gemm_h<<<g, 256, G_SMEM>>>(1, 1024, 2048); }
    // cross-merge (fp16 in)
    k_merge<<<8192, 256>>>(out);
}

// round 14
// speedup vs baseline: 1.0642x; 1.0642x over previous
#include <cuda_runtime.h>
#include <cuda_bf16.h>
#include <cuda_fp16.h>
#include <cstdint>
#include <math.h>

#define DEV __device__ __forceinline__

// ---------------- problem constants ----------------
// B=8, C=512, H=W=16, L=256, dim=128, chs=1024
// d_inner=2048, d_state=16, d_conv=4, dt_rank=64, 8 branches

// ---------------- scratch (device globals) ----------
__device__ float g_pool[8 * 512 * 275];
__device__ float g_cbr [8 * 128 * 275];
__device__ float g_p0map[8 * 128 * 256];
__device__ float g_p0  [8 * 128];
__device__ float g_xcT [8 * 256 * 1024];
__device__ float g_gw  [64];
__device__ float g_xdbl[8 * 8 * 256 * 96];         // x_proj output fp32 (B,C used by scan)

// fp16 operands / intermediates
__device__ __half g_xzf[8 * 8 * 256 * 4096];       // in_proj output (u|z) fp16
__device__ __half g_ysf[8 * 8 * 256 * 1024];       // out_proj output fp16
__device__ __half g_dtf[8 * 8 * 256 * 2048];       // softplus(dt) fp16
__device__ __half g_xgf[8 * 8 * 256 * 1024];       // fdgate out (single fp16)
__device__ __half g_y2f[8 * 8 * 256 * 2048];       // scan out (single fp16)
__device__ __half g_iwf[8 * 4096 * 1024];          // in_w fp16
__device__ __half g_owf[8 * 1024 * 2048];          // out_w fp16
__device__ __half g_uh [8 * 8 * 256 * 2048];       // u fp16 (single)
__device__ __half g_xpwh[8 * 96 * 2048];           // xp_w hi
__device__ __half g_xpwl[8 * 96 * 2048];           // xp_w lo
__device__ __half g_dtwh[8 * 2048 * 64];           // dtp_w fp16
__device__ __half g_xdh[8 * 8 * 256 * 64];         // xdbl[:, :64] fp16 (compact)

// ---------------- helpers ----------------
DEV float block_sum(float v, float* red) {
    int lane = threadIdx.x & 31, wid = threadIdx.x >> 5;
#pragma unroll
    for (int o = 16; o > 0; o >>= 1) v += __shfl_xor_sync(0xffffffffu, v, o);
    if (lane == 0) red[wid] = v;
    __syncthreads();
    if (wid == 0) {
        float w = (lane < 8) ? red[lane] : 0.f;
#pragma unroll
        for (int o = 4; o > 0; o >>= 1) w += __shfl_xor_sync(0xffffffffu, w, o);
        if (lane == 0) red[0] = w;
    }
    __syncthreads();
    float r = red[0];
    __syncthreads();
    return r;
}

DEV int pix_of(int k, int l) {
    int p = (k == 2 || k == 3 || k == 6 || k == 7) ? (255 - l) : l;
    switch (k) {
        case 0: case 2: return p;
        case 1: case 3: { int w = p >> 4, h = p & 15; return h * 16 + w; }
        case 4: case 6: { int wp = p >> 4, h = p & 15; int w = (h + wp) & 15; return h * 16 + w; }
        default:        { int wp = p >> 4, h = p & 15; int w = (wp - h) & 15; return h * 16 + w; }
    }
}

DEV void split_h(float v, __half& h, __half& l) {
    h = __float2half(v);
    l = __float2half(v - __half2float(h));
}

DEV unsigned smem_u32(const void* p) {
    unsigned a;
    asm("{ .reg .u64 t; cvta.to.shared.u64 t, %1; cvt.u32.u64 %0, t; }" : "=r"(a) : "l"(p));
    return a;
}

DEV void cp16(unsigned dst, const void* src) {
    asm volatile("cp.async.cg.shared.global [%0], [%1], 16;" :: "r"(dst), "l"(src));
}
DEV void cp_commit() { asm volatile("cp.async.commit_group;" ::: "memory"); }
template <int N> DEV void cp_wait() { asm volatile("cp.async.wait_group %0;" :: "n"(N) : "memory"); }

DEV void ldmx4(unsigned* r, unsigned addr) {
    asm volatile("ldmatrix.sync.aligned.m8n8.x4.shared.b16 {%0,%1,%2,%3}, [%4];"
                 : "=r"(r[0]), "=r"(r[1]), "=r"(r[2]), "=r"(r[3]) : "r"(addr));
}
DEV void mma_f16(float* d, const unsigned* a, const unsigned* b) {
    asm volatile(
        "mma.sync.aligned.m16n8k16.row.col.f32.f16.f16.f32 "
        "{%0,%1,%2,%3}, {%4,%5,%6,%7}, {%8,%9}, {%0,%1,%2,%3};"
        : "+f"(d[0]), "+f"(d[1]), "+f"(d[2]), "+f"(d[3])
        : "r"(a[0]), "r"(a[1]), "r"(a[2]), "r"(a[3]), "r"(b[0]), "r"(b[1]));
}

// ---------------- stage 1: pyramid pooling ----------------
__global__ void k_pool(const float* __restrict__ x) {
    __shared__ float sx[256];
    int b = blockIdx.x / 512, c = blockIdx.x % 512;
    const float* xp = x + (b * 512 + c) * 256;
    for (int i = threadIdx.x; i < 256; i += blockDim.x) sx[i] = xp[i];
    __syncthreads();
    int t = threadIdx.x;
    if (t < 275) {
        int s, idx;
        if (t < 25)       { s = 5;  idx = t; }
        else if (t < 106) { s = 9;  idx = t - 25; }
        else              { s = 13; idx = t - 106; }
        int i = idx / s, j = idx % s;
        int r0 = i * 16 / s, r1 = ((i + 1) * 16 + s - 1) / s;
        int c0 = j * 16 / s, c1 = ((j + 1) * 16 + s - 1) / s;
        float sum = 0.f;
        for (int r = r0; r < r1; r++)
            for (int cc = c0; cc < c1; cc++) sum += sx[r * 16 + cc];
        g_pool[(b * 512 + c) * 275 + t] = sum / (float)((r1 - r0) * (c1 - c0));
    }
}

// ---------------- CBR as tiled GEMM ----------------------------------------
__global__ void __launch_bounds__(256)
k_cbr_gemm(const float* __restrict__ x, int useX, int off, int posCnt, int scale,
           const float* __restrict__ pw, const float* __restrict__ bn_g,
           const float* __restrict__ bn_b, int tilesPerB) {
    int b = blockIdx.x / tilesPerB, tile = blockIdx.x % tilesPerB;
    int pos0 = tile * 32;
    if (pos0 >= posCnt) return;
    __shared__ float ws[128][33];
    __shared__ float ps[32][33];
    int tid = threadIdx.x, lane = tid & 31, warp = tid >> 5;
    int tx = tid & 7, ty = tid >> 3;
    int ldS = useX ? 256 : 275;
    const float* src = useX ? x : (const float*)g_pool;
    float acc[4][4];
#pragma unroll
    for (int i = 0; i < 4; i++)
#pragma unroll
        for (int j = 0; j < 4; j++) acc[i][j] = 0.f;

    for (int k0 = 0; k0 < 512; k0 += 32) {
#pragma unroll
        for (int i = 0; i < 16; i++) {
            int o = warp * 16 + i;
            ws[o][lane] = pw[(long)(scale * 128 + o) * 512 + k0 + lane];
        }
#pragma unroll
        for (int i = 0; i < 4; i++) {
            int kc = warp * 4 + i, c = k0 + kc;
            int p = pos0 + lane;
            ps[kc][lane] = (p < posCnt) ? src[((long)b * 512 + c) * ldS + off + p] : 0.f;
        }
        __syncthreads();
#pragma unroll
        for (int kc = 0; kc < 32; kc++) {
            float a0 = ws[ty * 4 + 0][kc], a1 = ws[ty * 4 + 1][kc];
            float a2 = ws[ty * 4 + 2][kc], a3 = ws[ty * 4 + 3][kc];
            float p0 = ps[kc][tx * 4 + 0], p1 = ps[kc][tx * 4 + 1];
            float p2 = ps[kc][tx * 4 + 2], p3 = ps[kc][tx * 4 + 3];
            acc[0][0] += a0 * p0; acc[0][1] += a0 * p1; acc[0][2] += a0 * p2; acc[0][3] += a0 * p3;
            acc[1][0] += a1 * p0; acc[1][1] += a1 * p1; acc[1][2] += a1 * p2; acc[1][3] += a1 * p3;
            acc[2][0] += a2 * p0; acc[2][1] += a2 * p1; acc[2][2] += a2 * p2; acc[2][3] += a2 * p3;
            acc[3][0] += a3 * p0; acc[3][1] += a3 * p1; acc[3][2] += a3 * p2; acc[3][3] += a3 * p3;
        }
        __syncthreads();
    }
    float gsc = rsqrtf(1.f + 1e-5f);
#pragma unroll
    for (int i = 0; i < 4; i++) {
        int o = ty * 4 + i;
        float g = bn_g[scale * 128 + o] * gsc;
        float bb = bn_b[scale * 128 + o];
#pragma unroll
        for (int j = 0; j < 4; j++) {
            int p = pos0 + tx * 4 + j;
            if (p < posCnt) {
                float v = fminf(fmaxf(acc[i][j] * g + bb, 0.f), 6.f);
                if (useX) g_p0map[((long)b * 128 + o) * 256 + p] = v;
                else      g_cbr [((long)b * 128 + o) * 275 + off + p] = v;
            }
        }
    }
}

__global__ void k_p0_reduce() {
    int b = blockIdx.x >> 7, o = blockIdx.x & 127;
    __shared__ float red[256];
    int p = threadIdx.x;
    red[p] = g_p0map[((long)b * 128 + o) * 256 + p];
    __syncthreads();
    for (int st = 128; st > 0; st >>= 1) { if (p < st) red[p] += red[p + st]; __syncthreads(); }
    if (p == 0) g_p0[b * 128 + o] = red[0] * (1.f / 256.f);
}

__global__ void k_assemble(const float* __restrict__ x) {
    int b = blockIdx.x / 256, pix = blockIdx.x % 256;
    int h = pix / 16, w = pix % 16;
    float* out = g_xcT + (b * 256 + pix) * 1024;
    for (int i = 0; i < 4; i++) {
        int c = threadIdx.x + i * 256;
        float v;
        if (c < 128) {
            v = g_p0[b * 128 + c];
        } else if (c < 512) {
            int sc = (c - 128) / 128, o = (c - 128) % 128;
            int s   = sc == 0 ? 5 : (sc == 1 ? 9 : 13);
            int off = sc == 0 ? 0 : (sc == 1 ? 25 : 106);
            float fy = (h + 0.5f) * s * (1.f / 16.f) - 0.5f;
            float fx = (w + 0.5f) * s * (1.f / 16.f) - 0.5f;
            int y0 = (int)floorf(fy), x0 = (int)floorf(fx);
            float wy = fy - y0, wx = fx - x0;
            int y1 = min(y0 + 1, s - 1), x1 = min(x0 + 1, s - 1);
            y0 = max(y0, 0); x0 = max(x0, 0);
            const float* base = g_cbr + (b * 128 + o) * 275 + off;
            float v00 = base[y0 * s + x0], v01 = base[y0 * s + x1];
            float v10 = base[y1 * s + x0], v11 = base[y1 * s + x1];
            v = v00 * (1 - wy) * (1 - wx) + v01 * (1 - wy) * wx
              + v10 * wy * (1 - wx) + v11 * wy * wx;
        } else {
            v = x[(b * 512 + (c - 512)) * 256 + pix];
        }
        out[c] = v;
    }
}

// ---------------- stage 2: gate weights (softmax + top4) ----------------
__global__ void k_gate_weights(const float* __restrict__ gate_w) {
    __shared__ float sm[1024];
    __shared__ float slog[8];
    int b = blockIdx.x, t = threadIdx.x;
    float s = 0.f;
    const float* base = g_xcT + b * 256 * 1024;
    for (int p = 0; p < 256; p++) s += base[p * 1024 + t];
    sm[t] = s * (1.f / 256.f);
    __syncthreads();
    if (t < 256) {
        int k = t / 32, lane = t % 32;
        float acc = 0.f;
        for (int c = lane; c < 1024; c += 32) acc += sm[c] * gate_w[k * 1024 + c];
#pragma unroll
        for (int o = 16; o > 0; o >>= 1) acc += __shfl_down_sync(0xffffffffu, acc, o);
        if (lane == 0) slog[k] = acc;
    }
    __syncthreads();
    if (t == 0) {
        float mx = -1e30f;
        for (int k = 0; k < 8; k++) mx = fmaxf(mx, slog[k]);
        float e[8], se = 0.f;
        for (int k = 0; k < 8; k++) { e[k] = expf(slog[k] - mx); se += e[k]; }
        float sc[8];
        for (int k = 0; k < 8; k++) sc[k] = e[k] / se;
        float gwv[8];
        bool used[8];
        for (int k = 0; k < 8; k++) { gwv[k] = 0.f; used[k] = false; }
        for (int r = 0; r < 4; r++) {
            int bi = -1; float bv = -1e30f;
            for (int k = 0; k < 8; k++)
                if (!used[k] && sc[k] > bv) { bv = sc[k]; bi = k; }
            used[bi] = true; gwv[bi] = bv;
        }
        for (int k = 0; k < 8; k++) g_gw[b * 8 + k] = gwv[k];
    }
}

// ---------------- stage 3: cross-scan + fd_gate -> xg (fp16) ---------------
__global__ void k_fdgate(const float* __restrict__ ln_g, const float* __restrict__ ln_b,
                         const float* __restrict__ fd_scale) {
    int z = blockIdx.x;
    int l = z & 255, k = (z >> 8) & 7, b = z >> 11;
    if (g_gw[b * 8 + k] == 0.f) return;
    int pix = pix_of(k, l);
    int pixp = (l > 0) ? pix_of(k, l - 1) : -1;
    const float* cur = g_xcT + (b * 256 + pix) * 1024;
    const float* prv = (pixp >= 0) ? g_xcT + (b * 256 + pixp) * 1024 : nullptr;
    __shared__ float red[32];
    int t = threadIdx.x;
    float xv[4], dv[4];
    float s1 = 0.f, s2 = 0.f;
#pragma unroll
    for (int i = 0; i < 4; i++) {
        int c = t + i * 256;
        xv[i] = cur[c];
        float pvv = prv ? prv[c] : 0.f;
        dv[i] = xv[i] - pvv;
        s1 += dv[i];
        s2 += dv[i] * dv[i];
    }
    float S1 = block_sum(s1, red);
    float S2 = block_sum(s2, red);
    float mu = S1 * (1.f / 1024.f);
    float var = S2 * (1.f / 1024.f) - mu * mu;
    float rstd = rsqrtf(var + 1e-5f);
    float s3 = 0.f;
#pragma unroll
    for (int i = 0; i < 4; i++) {
        int c = t + i * 256;
        float dn = (dv[i] - mu) * rstd * ln_g[c] + ln_b[c];
        s3 += dn * dn;
    }
    float S3 = block_sum(s3, red);
    float nd = sqrtf(S3) * fd_scale[0];
    float gate = 0.2f + 0.8f * tanhf(fabsf(nd));
    long rowoff = ((long)(b * 8 + k) * 256 + l) * 1024;
#pragma unroll
    for (int i = 0; i < 4; i++) {
        int c = t + i * 256;
        g_xgf[rowoff + c] = __float2half(xv[i] * gate);
    }
}

// ---------------- weight conversions ----------------------------------------
__global__ void k_split4(const float4* __restrict__ src, int which, int n4) {
    int i = blockIdx.x * 256 + threadIdx.x;
    if (i >= n4) return;
    float4 v = src[i];
    __half2 a = __floats2half2_rn(v.x, v.y);
    __half2 b = __floats2half2_rn(v.z, v.w);
    __half2* dst = (which == 0) ? (__half2*)g_iwf : (__half2*)g_owf;
    dst[i * 2]     = a;
    dst[i * 2 + 1] = b;
}
// which: 2 -> xp_w hi/lo split, 3 -> dtp_w fp16 only
__global__ void k_split(const float* __restrict__ src, int which, int n) {
    int i = blockIdx.x * 256 + threadIdx.x;
    if (i >= n) return;
    float v = src[i];
    if (which == 2) { __half h, l; split_h(v, h, l); g_xpwh[i] = h; g_xpwl[i] = l; }
    else            { g_dtwh[i] = __float2half(v); }
}

// ---------------- fp16 HMMA GEMM (K-chunk 64, 3-stage ring, fp16 out) -------
#define RS144 144               // row stride bytes (64 halves + 8 pad)
#define MATB64 (128 * RS144)    // 18432 bytes per matrix
#define G_OFF_A 0
#define G_OFF_B (MATB64)
#define G_STAGE (2 * MATB64)    // 36864
#define G_NSTAGE 3
#define G_SMEM (G_NSTAGE * G_STAGE)  // 110592

DEV void issue64(unsigned sbs, const __half* __restrict__ A, const __half* __restrict__ Bm,
                 int K, int k0, int tid) {
#pragma unroll
    for (int i = 0; i < 4; i++) {
        int idx = tid + i * 256;
        int row = idx >> 3, g = idx & 7;
        cp16(sbs + G_OFF_A + row * RS144 + g * 16, A + (long)row * K + k0 + g * 8);
        cp16(sbs + G_OFF_B + row * RS144 + g * 16, Bm + (long)row * K + k0 + g * 8);
    }
    cp_commit();
}

// sel: 0 -> A=g_xgf (K=1024), B=g_iwf (N=4096), C=g_xzf
//      1 -> A=g_y2f (K=2048), B=g_owf (N=1024), C=g_ysf
__global__ void __launch_bounds__(256)
k_gemm_h(int sel, int N, int K) {
    int zi = blockIdx.z;
    int kk = zi >> 3, b = zi & 7;
    int z = b * 8 + kk;
    if (g_gw[z] == 0.f) return;

    const __half *A, *Bm;
    __half* C;
    if (sel == 0) {
        A  = g_xgf + (long)z * 256 * 1024;
        Bm = g_iwf + (long)kk * 4096 * 1024;
        C  = g_xzf + (long)z * 256 * 4096;
    } else {
        A  = g_y2f + (long)z * 256 * 2048;
        Bm = g_owf + (long)kk * 1024 * 2048;
        C  = g_ysf + (long)z * 256 * 1024;
    }

    int bm = blockIdx.y * 128, bn = blockIdx.x * 128;
    A  += (long)bm * K;
    Bm += (long)bn * K;

    extern __shared__ char dsm[];
    unsigned sb0 = smem_u32(dsm);
    int tid = threadIdx.x;
    int lane = tid & 31, warp = tid >> 5;
    int wm = (warp & 1) * 64, wn = (warp >> 1) * 32;
    int mi = lane >> 3, lr = lane & 7;
    int arow = (mi & 1) * 8 + lr;
    int akb  = (mi >> 1) * 16;
    int brow = (mi >> 1) * 8 + lr;
    int bkb  = (mi & 1) * 16;

    float acc[4][4][4];
#pragma unroll
    for (int i = 0; i < 4; i++)
#pragma unroll
        for (int j = 0; j < 4; j++)
#pragma unroll
            for (int r = 0; r < 4; r++) acc[i][j][r] = 0.f;

    int nk = K >> 6;

    issue64(sb0 + 0 * G_STAGE, A, Bm, K, 0, tid);
    issue64(sb0 + 1 * G_STAGE, A, Bm, K, 64, tid);
    cp_commit();   // empty pad group

    for (int j = 0; j < nk; j++) {
        cp_wait<2>();
        __syncthreads();
        if (j + 2 < nk) issue64(sb0 + ((j + 2) % 3) * G_STAGE, A, Bm, K, (j + 2) << 6, tid);
        else            cp_commit();
        unsigned sbs = sb0 + (j % 3) * G_STAGE;
#pragma unroll
        for (int ks = 0; ks < 4; ks++) {
            unsigned kb = ks * 32;
            unsigned ah[4][4];
#pragma unroll
            for (int mf = 0; mf < 4; mf++) {
                unsigned ro = (wm + mf * 16 + arow) * RS144 + kb + akb;
                ldmx4(ah[mf], sbs + G_OFF_A + ro);
            }
            unsigned bh[2][4];
#pragma unroll
            for (int p = 0; p < 2; p++) {
                unsigned ro = (wn + p * 16 + brow) * RS144 + kb + bkb;
                ldmx4(bh[p], sbs + G_OFF_B + ro);
            }
#pragma unroll
            for (int mf = 0; mf < 4; mf++)
#pragma unroll
                for (int nf = 0; nf < 4; nf++) {
                    const unsigned* bhp = &bh[nf >> 1][(nf & 1) * 2];
                    mma_f16(acc[mf][nf], ah[mf], bhp);
                }
        }
    }

    int g = lane >> 2, tI = lane & 3;
#pragma unroll
    for (int mf = 0; mf < 4; mf++) {
        int r0 = bm + wm + mf * 16 + g;
#pragma unroll
        for (int nf = 0; nf < 4; nf++) {
            int col = bn + wn + nf * 8 + tI * 2;
            *(__half2*)(C + (long)r0 * N + col)       = __floats2half2_rn(acc[mf][nf][0], acc[mf][nf][1]);
            *(__half2*)(C + (long)(r0 + 8) * N + col) = __floats2half2_rn(acc[mf][nf][2], acc[mf][nf][3]);
        }
    }
}

// ---------------- HMMA x_dbl GEMM (A fp16, B hi/lo 2-term) ------------------
#define RS80 80
#define MAT_B (128 * RS80)
#define X_OFF_A  0
#define X_OFF_BH (MAT_B)
#define X_OFF_BL (2 * MAT_B)
#define X_STAGE (3 * MAT_B)     // 30720
#define X_GSMEM (2 * X_STAGE)   // 61440

__global__ void __launch_bounds__(256)
k_gemm_xdbl_h() {
    int z = blockIdx.y;
    int kk = z & 7;
    if (g_gw[z] == 0.f) return;
    const int K = 2048;
    const __half* A  = g_uh + (long)z * 256 * 2048;
    const __half* Bh = g_xpwh + (long)kk * 96 * 2048;
    const __half* Bl = g_xpwl + (long)kk * 96 * 2048;
    float* C = g_xdbl + (long)z * 256 * 96;
    __half* Dh = g_xdh + (long)z * 256 * 64;

    int bm = blockIdx.x * 128;
    A += (long)bm * K;

    extern __shared__ char dsm[];
    unsigned sb0 = smem_u32(dsm);
    int tid = threadIdx.x;
    int lane = tid & 31, warp = tid >> 5;
    int wm = (warp & 1) * 64, wn = (warp >> 1) * 24;
    int mi = lane >> 3, lr = lane & 7;
    int arow = (mi & 1) * 8 + lr;
    int akb  = (mi >> 1) * 16;
    int brow = (mi >> 1) * 8 + lr;
    int bkb  = (mi & 1) * 16;

    float acc[4][3][4];
#pragma unroll
    for (int i = 0; i < 4; i++)
#pragma unroll
        for (int j = 0; j < 3; j++)
#pragma unroll
            for (int r = 0; r < 4; r++) acc[i][j][r] = 0.f;

    int ci0 = tid * 2;
    int row0 = ci0 >> 2, kc0 = (ci0 & 3);
    int row1 = (ci0 + 1) >> 2, kc1 = ((ci0 + 1) & 3);
    int rb0 = row0 < 96 ? row0 : 95;
    int rb1 = row1 < 96 ? row1 : 95;

#define XISSUE(J, BUF)                                                                       \
    {                                                                                        \
        int k0 = (J) << 5;                                                                   \
        unsigned sbs = sb0 + (BUF) * X_STAGE;                                                \
        cp16(sbs + X_OFF_A  + row0 * RS80 + kc0 * 16, A  + (long)row0 * K + k0 + kc0 * 8);   \
        cp16(sbs + X_OFF_A  + row1 * RS80 + kc1 * 16, A  + (long)row1 * K + k0 + kc1 * 8);   \
        cp16(sbs + X_OFF_BH + row0 * RS80 + kc0 * 16, Bh + (long)rb0 * K + k0 + kc0 * 8);    \
        cp16(sbs + X_OFF_BH + row1 * RS80 + kc1 * 16, Bh + (long)rb1 * K + k0 + kc1 * 8);    \
        cp16(sbs + X_OFF_BL + row0 * RS80 + kc0 * 16, Bl + (long)rb0 * K + k0 + kc0 * 8);    \
        cp16(sbs + X_OFF_BL + row1 * RS80 + kc1 * 16, Bl + (long)rb1 * K + k0 + kc1 * 8);    \
        cp_commit();                                                                         \
    }

    const int nk = 64;
    XISSUE(0, 0);
    for (int j = 0; j < nk; j++) {
        if (j + 1 < nk) { XISSUE(j + 1, (j + 1) & 1); cp_wait<1>(); }
        else            { cp_wait<0>(); }
        __syncthreads();
        unsigned sbs = sb0 + (j & 1) * X_STAGE;
#pragma unroll
        for (int ks = 0; ks < 2; ks++) {
            unsigned kb = ks * 32;
            unsigned ah[4][4];
#pragma unroll
            for (int mf = 0; mf < 4; mf++) {
                unsigned ro = (wm + mf * 16 + arow) * RS80 + kb + akb;
                ldmx4(ah[mf], sbs + X_OFF_A + ro);
            }
            unsigned bh[2][4], bl[2][4];
#pragma unroll
            for (int p = 0; p < 2; p++) {
                unsigned ro = (wn + p * 16 + brow) * RS80 + kb + bkb;
                ldmx4(bh[p], sbs + X_OFF_BH + ro);
                ldmx4(bl[p], sbs + X_OFF_BL + ro);
            }
#pragma unroll
            for (int mf = 0; mf < 4; mf++)
#pragma unroll
                for (int nf = 0; nf < 3; nf++) {
                    const unsigned* bhp = &bh[nf >> 1][(nf & 1) * 2];
                    const unsigned* blp = &bl[nf >> 1][(nf & 1) * 2];
                    mma_f16(acc[mf][nf], ah[mf], bhp);
                    mma_f16(acc[mf][nf], ah[mf], blp);
                }
        }
        __syncthreads();
    }

    int g = lane >> 2, tI = lane & 3;
#pragma unroll
    for (int mf = 0; mf < 4; mf++) {
        int r0 = bm + wm + mf * 16 + g;
#pragma unroll
        for (int nf = 0; nf < 3; nf++) {
            int col = wn + nf * 8 + tI * 2;
#pragma unroll
            for (int half = 0; half < 2; half++) {
                int r = r0 + half * 8;
                float v0 = acc[mf][nf][half * 2 + 0];
                float v1 = acc[mf][nf][half * 2 + 1];
                C[(long)r * 96 + col]     = v0;
                C[(long)r * 96 + col + 1] = v1;
                if (col < 64) {
                    Dh[(long)r * 64 + col]     = __float2half(v0);
                    Dh[(long)r * 64 + col + 1] = __float2half(v1);
                }
            }
        }
    }
}

// ---------------- HMMA dt GEMM (plain fp16, K=64, fp16 out) -----------------
#define D_OFF_A 0
#define D_OFF_B (MAT_B)
#define D_STAGE (2 * MAT_B)     // 20480
#define D_GSMEM (2 * D_STAGE)   // 40960

__global__ void __launch_bounds__(256)
k_gemm_dt_h(const float* __restrict__ bias) {
    int z = blockIdx.z;
    int kk = z & 7;
    if (g_gw[z] == 0.f) return;
    const int K = 64, N = 2048;
    const __half* A = g_xdh + (long)z * 256 * 64;
    const __half* B = g_dtwh + (long)kk * 2048 * 64;
    __half* C = g_dtf + (long)z * 256 * 2048;

    int bm = blockIdx.y * 128, bn = blockIdx.x * 128;
    A += (long)bm * K;
    B += (long)bn * K;

    extern __shared__ char dsm[];
    unsigned sb0 = smem_u32(dsm);
    int tid = threadIdx.x;
    int lane = tid & 31, warp = tid >> 5;
    int wm = (warp & 1) * 64, wn = (warp >> 1) * 32;
    int mi = lane >> 3, lr = lane & 7;
    int arow = (mi & 1) * 8 + lr;
    int akb  = (mi >> 1) * 16;
    int brow = (mi >> 1) * 8 + lr;
    int bkb  = (mi & 1) * 16;

    float acc[4][4][4];
#pragma unroll
    for (int i = 0; i < 4; i++)
#pragma unroll
        for (int j = 0; j < 4; j++)
#pragma unroll
            for (int r = 0; r < 4; r++) acc[i][j][r] = 0.f;

    int ci0 = tid * 2;
    int row0 = ci0 >> 2, kc0 = (ci0 & 3);
    int row1 = (ci0 + 1) >> 2, kc1 = ((ci0 + 1) & 3);

#define DISSUE(J, BUF)                                                                      \
    {                                                                                       \
        int k0 = (J) << 5;                                                                  \
        unsigned sbs = sb0 + (BUF) * D_STAGE;                                               \
        cp16(sbs + D_OFF_A + row0 * RS80 + kc0 * 16, A + (long)row0 * K + k0 + kc0 * 8);    \
        cp16(sbs + D_OFF_A + row1 * RS80 + kc1 * 16, A + (long)row1 * K + k0 + kc1 * 8);    \
        cp16(sbs + D_OFF_B + row0 * RS80 + kc0 * 16, B + (long)row0 * K + k0 + kc0 * 8);    \
        cp16(sbs + D_OFF_B + row1 * RS80 + kc1 * 16, B + (long)row1 * K + k0 + kc1 * 8);    \
        cp_commit();                                                                        \
    }

    DISSUE(0, 0);
    DISSUE(1, 1);
    cp_wait<0>();
    __syncthreads();

#pragma unroll
    for (int j = 0; j < 2; j++) {
        unsigned sbs = sb0 + j * D_STAGE;
#pragma unroll
        for (int ks = 0; ks < 2; ks++) {
            unsigned kb = ks * 32;
            unsigned ah[4][4];
#pragma unroll
            for (int mf = 0; mf < 4; mf++) {
                unsigned ro = (wm + mf * 16 + arow) * RS80 + kb + akb;
                ldmx4(ah[mf], sbs + D_OFF_A + ro);
            }
            unsigned bh[2][4];
#pragma unroll
            for (int p = 0; p < 2; p++) {
                unsigned ro = (wn + p * 16 + brow) * RS80 + kb + bkb;
                ldmx4(bh[p], sbs + D_OFF_B + ro);
            }
#pragma unroll
            for (int mf = 0; mf < 4; mf++)
#pragma unroll
                for (int nf = 0; nf < 4; nf++) {
                    const unsigned* bhp = &bh[nf >> 1][(nf & 1) * 2];
                    mma_f16(acc[mf][nf], ah[mf], bhp);
                }
        }
    }

    int g = lane >> 2, tI = lane & 3;
#pragma unroll
    for (int mf = 0; mf < 4; mf++) {
        int r0 = bm + wm + mf * 16 + g;
#pragma unroll
        for (int nf = 0; nf < 4; nf++) {
            int col = bn + wn + nf * 8 + tI * 2;
            float b0 = bias[kk * N + col], b1 = bias[kk * N + col + 1];
#pragma unroll
            for (int half = 0; half < 2; half++) {
                int r = r0 + half * 8;
                float v0 = acc[mf][nf][half * 2 + 0] + b0;
                float v1 = acc[mf][nf][half * 2 + 1] + b1;
                v0 = (v0 > 20.f) ? v0 : log1pf(__expf(v0));
                v1 = (v1 > 20.f) ? v1 : log1pf(__expf(v1));
                C[(long)r * N + col]     = __float2half(v0);
                C[(long)r * N + col + 1] = __float2half(v1);
            }
        }
    }
}

// ---------------- depthwise causal conv (l-parallel, fp16 in/out) -----------
__global__ void k_conv(const float* __restrict__ cw, const float* __restrict__ cb) {
    int gb = blockIdx.x;
    int l = gb & 255, z = gb >> 8;
    int k = z & 7;
    if (g_gw[z] == 0.f) return;
    const __half* xzb = g_xzf + (long)z * 256 * 4096;
    long ubase = ((long)z * 256 + l) * 2048;
#pragma unroll
    for (int i = 0; i < 8; i++) {
        int d = threadIdx.x + i * 256;
        float4 w4 = ((const float4*)cw)[k * 2048 + d];
        float acc = cb[k * 2048 + d];
        float wv[4] = {w4.x, w4.y, w4.z, w4.w};
#pragma unroll
        for (int j = 0; j < 4; j++) {
            int lp = l - 3 + j;
            if (lp >= 0) acc += wv[j] * __half2float(xzb[(long)lp * 4096 + d]);
        }
        float u = acc / (1.f + __expf(-acc));  // silu
        g_uh[ubase + d] = __float2half(u);
    }
}

// ---------------- selective scan -> y2 fp16 ---------------------------------
__global__ void k_scan(const float* __restrict__ A_log, const float* __restrict__ D_p) {
    __shared__ float sbc[256 * 32];
    int gb = blockIdx.x;
    int z = gb >> 3, dblk = gb & 7;
    int k = z & 7;
    if (g_gw[z] == 0.f) return;
    for (int idx = threadIdx.x; idx < 8192; idx += 256)
        sbc[idx] = g_xdbl[((long)z * 256 + (idx >> 5)) * 96 + 64 + (idx & 31)];
    __syncthreads();
    int d = dblk * 256 + threadIdx.x;
    float a[16];
#pragma unroll
    for (int s = 0; s < 16; s++) a[s] = -__expf(A_log[(long)(k * 2048 + d) * 16 + s]);
    bool fast = true;
#pragma unroll
    for (int s = 0; s < 16; s++) {
        float r = a[s] / a[0];
        if (fabsf(r - (float)(s + 1)) > 1e-4f) fast = false;
    }
    float dp = D_p[k * 2048 + d];
    float h[16];
#pragma unroll
    for (int s = 0; s < 16; s++) h[s] = 0.f;
    const __half* dtb = g_dtf + (long)z * 256 * 2048 + d;
    const __half* uhb = g_uh + (long)z * 256 * 2048 + d;
    const __half* zb  = g_xzf + (long)z * 256 * 4096 + 2048 + d;
    long ybase = (long)z * 256 * 2048 + d;
    for (int l = 0; l < 256; l++) {
        float dt = __half2float(dtb[(long)l * 2048]);
        float uu = __half2float(uhb[(long)l * 2048]);
        float zz = __half2float(zb[(long)l * 4096]);
        float dtu = dt * uu;
        float acc = 0.f;
        const float* bc = &sbc[l * 32];
        if (fast) {
            float e = __expf(dt * a[0]);
            float p = 1.f;
#pragma unroll
            for (int s = 0; s < 16; s++) {
                p *= e;
                h[s] = p * h[s] + dtu * bc[s];
                acc += h[s] * bc[16 + s];
            }
        } else {
#pragma unroll
            for (int s = 0; s < 16; s++) {
                float e = __expf(dt * a[s]);
                h[s] = e * h[s] + dtu * bc[s];
                acc += h[s] * bc[16 + s];
            }
        }
        float y = acc + uu * dp;
        y *= zz / (1.f + __expf(-zz));  // * silu(z)
        g_y2f[ybase + (long)l * 2048] = __float2half(y);
    }
}

// ---------------- cross-merge (gather + gated sum, fp16 in) -----------------
__global__ void k_merge(float* __restrict__ out) {
    int t = blockIdx.x * 256 + threadIdx.x;
    int pix = t & 255, c = (t >> 8) & 1023, b = t >> 18;
    int h = pix >> 4, w = pix & 15;
    int l0 = pix;
    int l1 = w * 16 + h;
    int ld = ((w - h) & 15) * 16 + h;
    int la = ((w + h) & 15) * 16 + h;
    int pos[8] = {l0, l1, 255 - l0, 255 - l1, ld, la, 255 - ld, 255 - la};
    float acc = 0.f;
#pragma unroll
    for (int k = 0; k < 8; k++) {
        float g = g_gw[b * 8 + k];
        if (g != 0.f)
            acc += g * __half2float(g_ysf[((long)(b * 8 + k) * 256 + pos[k]) * 1024 + c]);
    }
    out[t] = acc;
}

// ---------------- launch ----------------
extern "C" void kernel_launch(void* const* d_in, const int* in_sizes, int n_in,
                              void* d_out, int out_size) {
    const float* x        = (const float*)d_in[0];
    const float* pw       = (const float*)d_in[1];
    const float* bn_g     = (const float*)d_in[2];
    const float* bn_b     = (const float*)d_in[3];
    const float* gate_w   = (const float*)d_in[4];
    const float* ln_g     = (const float*)d_in[5];
    const float* ln_b     = (const float*)d_in[6];
    const float* fd_scale = (const float*)d_in[7];
    const float* in_w     = (const float*)d_in[8];
    const float* cw       = (const float*)d_in[9];
    const float* cb       = (const float*)d_in[10];
    const float* xp_w     = (const float*)d_in[11];
    const float* dtp_w    = (const float*)d_in[12];
    const float* dtp_b    = (const float*)d_in[13];
    const float* A_log    = (const float*)d_in[14];
    const float* D_p      = (const float*)d_in[15];
    const float* out_w    = (const float*)d_in[16];
    float* out = (float*)d_out;

    cudaFuncSetAttribute(k_gemm_h, cudaFuncAttributeMaxDynamicSharedMemorySize, G_SMEM);
    cudaFuncSetAttribute(k_gemm_xdbl_h, cudaFuncAttributeMaxDynamicSharedMemorySize, X_GSMEM);
    cudaFuncSetAttribute(k_gemm_dt_h, cudaFuncAttributeMaxDynamicSharedMemorySize, D_GSMEM);

    // weight conversions (deterministic, every call)
    {
        int n1 = 8 * 4096 * 1024, n2 = 8 * 1024 * 2048;
        int n3 = 8 * 96 * 2048,   n4 = 8 * 2048 * 64;
        k_split4<<<(n1 / 4) / 256, 256>>>((const float4*)in_w, 0, n1 / 4);
        k_split4<<<(n2 / 4) / 256, 256>>>((const float4*)out_w, 1, n2 / 4);
        k_split<<<(n3 + 255) / 256, 256>>>(xp_w, 2, n3);
        k_split<<<(n4 + 255) / 256, 256>>>(dtp_w, 3, n4);
    }

    k_pool<<<8 * 512, 288>>>(x);
    k_cbr_gemm<<<8 * 8, 256>>>(x, 1, 0,   256, 0, pw, bn_g, bn_b, 8);   // p0 map
    k_cbr_gemm<<<8 * 1, 256>>>(x, 0, 0,    25, 1, pw, bn_g, bn_b, 1);   // s=5
    k_cbr_gemm<<<8 * 3, 256>>>(x, 0, 25,   81, 2, pw, bn_g, bn_b, 3);   // s=9
    k_cbr_gemm<<<8 * 6, 256>>>(x, 0, 106, 169, 3, pw, bn_g, bn_b, 6);   // s=13
    k_p0_reduce<<<8 * 128, 256>>>();
    k_assemble<<<8 * 256, 256>>>(x);
    k_gate_weights<<<8, 1024>>>(gate_w);
    k_fdgate<<<8 * 8 * 256, 256>>>(ln_g, ln_b, fd_scale);

    // in_proj (fp16 HMMA, K-chunk 64, fp16 out)
    { dim3 g(32, 2, 64); k_gemm_h<<<g, 256, G_SMEM>>>(0, 4096, 1024); }
    // depthwise conv + silu -> u fp16 (l-parallel)
    k_conv<<<64 * 256, 256>>>(cw, cb);
    // x_dbl (HMMA, A fp16 + B hi/lo 2-term)
    { dim3 g(2, 64); k_gemm_xdbl_h<<<g, 256, X_GSMEM>>>(); }
    // dt projection + softplus (plain fp16 HMMA)
    { dim3 g(16, 2, 64); k_gemm_dt_h<<<g, 256, D_GSMEM>>>(dtp_b); }
    // selective scan
    k_scan<<<64 * 8, 256>>>(A_log, D_p);
    // out_proj (fp16 HMMA, K-chunk 64, fp16 out)
    { dim3 g(8, 2, 64); k_gemm_h<<<g, 256, G_SMEM>>>(1, 1024, 2048); }
    // cross-merge (fp16 in)
    k_merge<<<8192, 256>>>(out);
}

// round 15
// speedup vs baseline: 1.0851x; 1.0197x over previous
#include <cuda_runtime.h>
#include <cuda_bf16.h>
#include <cuda_fp16.h>
#include <cstdint>
#include <math.h>

#define DEV __device__ __forceinline__

// ---------------- problem constants ----------------
// B=8, C=512, H=W=16, L=256, dim=128, chs=1024
// d_inner=2048, d_state=16, d_conv=4, dt_rank=64, 8 branches

// ---------------- scratch (device globals) ----------
__device__ float g_pool[8 * 512 * 275];
__device__ float g_cbr [8 * 128 * 275];
__device__ float g_p0map[8 * 128 * 256];
__device__ float g_p0  [8 * 128];
__device__ float g_xcT [8 * 256 * 1024];
__device__ float g_gw  [64];
__device__ float g_xdbl[8 * 8 * 256 * 96];         // x_proj output fp32 (B,C used by scan)

// fp16 operands / intermediates
__device__ __half g_xzf[8 * 8 * 256 * 4096];       // in_proj output (u|z) fp16
__device__ __half g_ysf[8 * 8 * 256 * 1024];       // out_proj output fp16
__device__ __half g_dtf[8 * 8 * 256 * 2048];       // softplus(dt) fp16
__device__ __half g_xgf[8 * 8 * 256 * 1024];       // fdgate out (single fp16)
__device__ __half g_y2f[8 * 8 * 256 * 2048];       // scan out (single fp16)
__device__ __half g_iwf[8 * 4096 * 1024];          // in_w fp16
__device__ __half g_owf[8 * 1024 * 2048];          // out_w fp16
__device__ __half g_uh [8 * 8 * 256 * 2048];       // u fp16 (single)
__device__ __half g_xpwh[8 * 96 * 2048];           // xp_w hi
__device__ __half g_xpwl[8 * 96 * 2048];           // xp_w lo
__device__ __half g_dtwh[8 * 2048 * 64];           // dtp_w fp16
__device__ __half g_xdh[8 * 8 * 256 * 64];         // xdbl[:, :64] fp16 (compact)

// ---------------- helpers ----------------
DEV float block_sum(float v, float* red) {
    int lane = threadIdx.x & 31, wid = threadIdx.x >> 5;
#pragma unroll
    for (int o = 16; o > 0; o >>= 1) v += __shfl_xor_sync(0xffffffffu, v, o);
    if (lane == 0) red[wid] = v;
    __syncthreads();
    if (wid == 0) {
        float w = (lane < 8) ? red[lane] : 0.f;
#pragma unroll
        for (int o = 4; o > 0; o >>= 1) w += __shfl_xor_sync(0xffffffffu, w, o);
        if (lane == 0) red[0] = w;
    }
    __syncthreads();
    float r = red[0];
    __syncthreads();
    return r;
}

// fused two-value block sum (8 warps): a -> red[0], b -> red[1]
DEV void block_sum2(float& a, float& b, float* red) {
    int lane = threadIdx.x & 31, wid = threadIdx.x >> 5;
#pragma unroll
    for (int o = 16; o > 0; o >>= 1) {
        a += __shfl_xor_sync(0xffffffffu, a, o);
        b += __shfl_xor_sync(0xffffffffu, b, o);
    }
    if (lane == 0) { red[wid] = a; red[8 + wid] = b; }
    __syncthreads();
    if (wid == 0) {
        float w = (lane < 16) ? red[lane] : 0.f;
#pragma unroll
        for (int o = 4; o > 0; o >>= 1) w += __shfl_xor_sync(0xffffffffu, w, o);
        if (lane == 0) red[0] = w;
        if (lane == 8) red[1] = w;
    }
    __syncthreads();
    a = red[0];
    b = red[1];
    __syncthreads();
}

DEV int pix_of(int k, int l) {
    int p = (k == 2 || k == 3 || k == 6 || k == 7) ? (255 - l) : l;
    switch (k) {
        case 0: case 2: return p;
        case 1: case 3: { int w = p >> 4, h = p & 15; return h * 16 + w; }
        case 4: case 6: { int wp = p >> 4, h = p & 15; int w = (h + wp) & 15; return h * 16 + w; }
        default:        { int wp = p >> 4, h = p & 15; int w = (wp - h) & 15; return h * 16 + w; }
    }
}

DEV void split_h(float v, __half& h, __half& l) {
    h = __float2half(v);
    l = __float2half(v - __half2float(h));
}

DEV unsigned smem_u32(const void* p) {
    unsigned a;
    asm("{ .reg .u64 t; cvta.to.shared.u64 t, %1; cvt.u32.u64 %0, t; }" : "=r"(a) : "l"(p));
    return a;
}

DEV void cp16(unsigned dst, const void* src) {
    asm volatile("cp.async.cg.shared.global [%0], [%1], 16;" :: "r"(dst), "l"(src));
}
DEV void cp_commit() { asm volatile("cp.async.commit_group;" ::: "memory"); }
template <int N> DEV void cp_wait() { asm volatile("cp.async.wait_group %0;" :: "n"(N) : "memory"); }

DEV void ldmx4(unsigned* r, unsigned addr) {
    asm volatile("ldmatrix.sync.aligned.m8n8.x4.shared.b16 {%0,%1,%2,%3}, [%4];"
                 : "=r"(r[0]), "=r"(r[1]), "=r"(r[2]), "=r"(r[3]) : "r"(addr));
}
DEV void mma_f16(float* d, const unsigned* a, const unsigned* b) {
    asm volatile(
        "mma.sync.aligned.m16n8k16.row.col.f32.f16.f16.f32 "
        "{%0,%1,%2,%3}, {%4,%5,%6,%7}, {%8,%9}, {%0,%1,%2,%3};"
        : "+f"(d[0]), "+f"(d[1]), "+f"(d[2]), "+f"(d[3])
        : "r"(a[0]), "r"(a[1]), "r"(a[2]), "r"(a[3]), "r"(b[0]), "r"(b[1]));
}

// ---------------- stage 1: pyramid pooling ----------------
__global__ void k_pool(const float* __restrict__ x) {
    __shared__ float sx[256];
    int b = blockIdx.x / 512, c = blockIdx.x % 512;
    const float* xp = x + (b * 512 + c) * 256;
    for (int i = threadIdx.x; i < 256; i += blockDim.x) sx[i] = xp[i];
    __syncthreads();
    int t = threadIdx.x;
    if (t < 275) {
        int s, idx;
        if (t < 25)       { s = 5;  idx = t; }
        else if (t < 106) { s = 9;  idx = t - 25; }
        else              { s = 13; idx = t - 106; }
        int i = idx / s, j = idx % s;
        int r0 = i * 16 / s, r1 = ((i + 1) * 16 + s - 1) / s;
        int c0 = j * 16 / s, c1 = ((j + 1) * 16 + s - 1) / s;
        float sum = 0.f;
        for (int r = r0; r < r1; r++)
            for (int cc = c0; cc < c1; cc++) sum += sx[r * 16 + cc];
        g_pool[(b * 512 + c) * 275 + t] = sum / (float)((r1 - r0) * (c1 - c0));
    }
}

// ---------------- CBR as tiled GEMM ----------------------------------------
__global__ void __launch_bounds__(256)
k_cbr_gemm(const float* __restrict__ x, int useX, int off, int posCnt, int scale,
           const float* __restrict__ pw, const float* __restrict__ bn_g,
           const float* __restrict__ bn_b, int tilesPerB) {
    int b = blockIdx.x / tilesPerB, tile = blockIdx.x % tilesPerB;
    int pos0 = tile * 32;
    if (pos0 >= posCnt) return;
    __shared__ float ws[128][33];
    __shared__ float ps[32][33];
    int tid = threadIdx.x, lane = tid & 31, warp = tid >> 5;
    int tx = tid & 7, ty = tid >> 3;
    int ldS = useX ? 256 : 275;
    const float* src = useX ? x : (const float*)g_pool;
    float acc[4][4];
#pragma unroll
    for (int i = 0; i < 4; i++)
#pragma unroll
        for (int j = 0; j < 4; j++) acc[i][j] = 0.f;

    for (int k0 = 0; k0 < 512; k0 += 32) {
#pragma unroll
        for (int i = 0; i < 16; i++) {
            int o = warp * 16 + i;
            ws[o][lane] = pw[(long)(scale * 128 + o) * 512 + k0 + lane];
        }
#pragma unroll
        for (int i = 0; i < 4; i++) {
            int kc = warp * 4 + i, c = k0 + kc;
            int p = pos0 + lane;
            ps[kc][lane] = (p < posCnt) ? src[((long)b * 512 + c) * ldS + off + p] : 0.f;
        }
        __syncthreads();
#pragma unroll
        for (int kc = 0; kc < 32; kc++) {
            float a0 = ws[ty * 4 + 0][kc], a1 = ws[ty * 4 + 1][kc];
            float a2 = ws[ty * 4 + 2][kc], a3 = ws[ty * 4 + 3][kc];
            float p0 = ps[kc][tx * 4 + 0], p1 = ps[kc][tx * 4 + 1];
            float p2 = ps[kc][tx * 4 + 2], p3 = ps[kc][tx * 4 + 3];
            acc[0][0] += a0 * p0; acc[0][1] += a0 * p1; acc[0][2] += a0 * p2; acc[0][3] += a0 * p3;
            acc[1][0] += a1 * p0; acc[1][1] += a1 * p1; acc[1][2] += a1 * p2; acc[1][3] += a1 * p3;
            acc[2][0] += a2 * p0; acc[2][1] += a2 * p1; acc[2][2] += a2 * p2; acc[2][3] += a2 * p3;
            acc[3][0] += a3 * p0; acc[3][1] += a3 * p1; acc[3][2] += a3 * p2; acc[3][3] += a3 * p3;
        }
        __syncthreads();
    }
    float gsc = rsqrtf(1.f + 1e-5f);
#pragma unroll
    for (int i = 0; i < 4; i++) {
        int o = ty * 4 + i;
        float g = bn_g[scale * 128 + o] * gsc;
        float bb = bn_b[scale * 128 + o];
#pragma unroll
        for (int j = 0; j < 4; j++) {
            int p = pos0 + tx * 4 + j;
            if (p < posCnt) {
                float v = fminf(fmaxf(acc[i][j] * g + bb, 0.f), 6.f);
                if (useX) g_p0map[((long)b * 128 + o) * 256 + p] = v;
                else      g_cbr [((long)b * 128 + o) * 275 + off + p] = v;
            }
        }
    }
}

__global__ void k_p0_reduce() {
    int b = blockIdx.x >> 7, o = blockIdx.x & 127;
    __shared__ float red[256];
    int p = threadIdx.x;
    red[p] = g_p0map[((long)b * 128 + o) * 256 + p];
    __syncthreads();
    for (int st = 128; st > 0; st >>= 1) { if (p < st) red[p] += red[p + st]; __syncthreads(); }
    if (p == 0) g_p0[b * 128 + o] = red[0] * (1.f / 256.f);
}

__global__ void k_assemble(const float* __restrict__ x) {
    int b = blockIdx.x / 256, pix = blockIdx.x % 256;
    int h = pix / 16, w = pix % 16;
    float* out = g_xcT + (b * 256 + pix) * 1024;
    for (int i = 0; i < 4; i++) {
        int c = threadIdx.x + i * 256;
        float v;
        if (c < 128) {
            v = g_p0[b * 128 + c];
        } else if (c < 512) {
            int sc = (c - 128) / 128, o = (c - 128) % 128;
            int s   = sc == 0 ? 5 : (sc == 1 ? 9 : 13);
            int off = sc == 0 ? 0 : (sc == 1 ? 25 : 106);
            float fy = (h + 0.5f) * s * (1.f / 16.f) - 0.5f;
            float fx = (w + 0.5f) * s * (1.f / 16.f) - 0.5f;
            int y0 = (int)floorf(fy), x0 = (int)floorf(fx);
            float wy = fy - y0, wx = fx - x0;
            int y1 = min(y0 + 1, s - 1), x1 = min(x0 + 1, s - 1);
            y0 = max(y0, 0); x0 = max(x0, 0);
            const float* base = g_cbr + (b * 128 + o) * 275 + off;
            float v00 = base[y0 * s + x0], v01 = base[y0 * s + x1];
            float v10 = base[y1 * s + x0], v11 = base[y1 * s + x1];
            v = v00 * (1 - wy) * (1 - wx) + v01 * (1 - wy) * wx
              + v10 * wy * (1 - wx) + v11 * wy * wx;
        } else {
            v = x[(b * 512 + (c - 512)) * 256 + pix];
        }
        out[c] = v;
    }
}

// ---------------- stage 2: gate weights (softmax + top4) ----------------
__global__ void k_gate_weights(const float* __restrict__ gate_w) {
    __shared__ float sm[1024];
    __shared__ float slog[8];
    int b = blockIdx.x, t = threadIdx.x;
    float s = 0.f;
    const float* base = g_xcT + b * 256 * 1024;
    for (int p = 0; p < 256; p++) s += base[p * 1024 + t];
    sm[t] = s * (1.f / 256.f);
    __syncthreads();
    if (t < 256) {
        int k = t / 32, lane = t % 32;
        float acc = 0.f;
        for (int c = lane; c < 1024; c += 32) acc += sm[c] * gate_w[k * 1024 + c];
#pragma unroll
        for (int o = 16; o > 0; o >>= 1) acc += __shfl_down_sync(0xffffffffu, acc, o);
        if (lane == 0) slog[k] = acc;
    }
    __syncthreads();
    if (t == 0) {
        float mx = -1e30f;
        for (int k = 0; k < 8; k++) mx = fmaxf(mx, slog[k]);
        float e[8], se = 0.f;
        for (int k = 0; k < 8; k++) { e[k] = expf(slog[k] - mx); se += e[k]; }
        float sc[8];
        for (int k = 0; k < 8; k++) sc[k] = e[k] / se;
        float gwv[8];
        bool used[8];
        for (int k = 0; k < 8; k++) { gwv[k] = 0.f; used[k] = false; }
        for (int r = 0; r < 4; r++) {
            int bi = -1; float bv = -1e30f;
            for (int k = 0; k < 8; k++)
                if (!used[k] && sc[k] > bv) { bv = sc[k]; bi = k; }
            used[bi] = true; gwv[bi] = bv;
        }
        for (int k = 0; k < 8; k++) g_gw[b * 8 + k] = gwv[k];
    }
}

// ---------------- stage 3: cross-scan + fd_gate -> xg (fp16) ---------------
__global__ void k_fdgate(const float* __restrict__ ln_g, const float* __restrict__ ln_b,
                         const float* __restrict__ fd_scale) {
    int z = blockIdx.x;
    int l = z & 255, k = (z >> 8) & 7, b = z >> 11;
    if (g_gw[b * 8 + k] == 0.f) return;
    int pix = pix_of(k, l);
    int pixp = (l > 0) ? pix_of(k, l - 1) : -1;
    const float* cur = g_xcT + (b * 256 + pix) * 1024;
    const float* prv = (pixp >= 0) ? g_xcT + (b * 256 + pixp) * 1024 : nullptr;
    __shared__ float red[32];
    int t = threadIdx.x;
    float xv[4], dv[4];
    float s1 = 0.f, s2 = 0.f;
#pragma unroll
    for (int i = 0; i < 4; i++) {
        int c = t + i * 256;
        xv[i] = cur[c];
        float pvv = prv ? prv[c] : 0.f;
        dv[i] = xv[i] - pvv;
        s1 += dv[i];
        s2 += dv[i] * dv[i];
    }
    block_sum2(s1, s2, red);
    float mu = s1 * (1.f / 1024.f);
    float var = s2 * (1.f / 1024.f) - mu * mu;
    float rstd = rsqrtf(var + 1e-5f);
    float s3 = 0.f;
#pragma unroll
    for (int i = 0; i < 4; i++) {
        int c = t + i * 256;
        float dn = (dv[i] - mu) * rstd * ln_g[c] + ln_b[c];
        s3 += dn * dn;
    }
    float S3 = block_sum(s3, red);
    float nd = sqrtf(S3) * fd_scale[0];
    float gate = 0.2f + 0.8f * tanhf(fabsf(nd));
    long rowoff = ((long)(b * 8 + k) * 256 + l) * 1024;
#pragma unroll
    for (int i = 0; i < 4; i++) {
        int c = t + i * 256;
        g_xgf[rowoff + c] = __float2half(xv[i] * gate);
    }
}

// ---------------- fused weight conversions (one launch) ---------------------
// segments: [0, N1) in_w vec4 -> g_iwf ; [N1, N1+N2) out_w vec4 -> g_owf ;
//           [.., +N3) xp_w hi/lo ; [.., +N4) dtp_w fp16
#define SP_N1 (8L * 4096 * 1024 / 4)
#define SP_N2 (8L * 1024 * 2048 / 4)
#define SP_N3 (8L * 96 * 2048)
#define SP_N4 (8L * 2048 * 64)
#define SP_TOT (SP_N1 + SP_N2 + SP_N3 + SP_N4)

__global__ void k_split_all(const float4* __restrict__ in_w, const float4* __restrict__ out_w,
                            const float* __restrict__ xp_w, const float* __restrict__ dtp_w) {
    long i = (long)blockIdx.x * 256 + threadIdx.x;
    if (i < SP_N1) {
        float4 v = in_w[i];
        __half2* dst = (__half2*)g_iwf;
        dst[i * 2]     = __floats2half2_rn(v.x, v.y);
        dst[i * 2 + 1] = __floats2half2_rn(v.z, v.w);
    } else if (i < SP_N1 + SP_N2) {
        long j = i - SP_N1;
        float4 v = out_w[j];
        __half2* dst = (__half2*)g_owf;
        dst[j * 2]     = __floats2half2_rn(v.x, v.y);
        dst[j * 2 + 1] = __floats2half2_rn(v.z, v.w);
    } else if (i < SP_N1 + SP_N2 + SP_N3) {
        long j = i - SP_N1 - SP_N2;
        __half h, l;
        split_h(xp_w[j], h, l);
        g_xpwh[j] = h;
        g_xpwl[j] = l;
    } else if (i < SP_TOT) {
        long j = i - SP_N1 - SP_N2 - SP_N3;
        g_dtwh[j] = __float2half(dtp_w[j]);
    }
}

// ---------------- fp16 HMMA GEMM (K-chunk 64, 3-stage ring, fp16 out) -------
#define RS144 144               // row stride bytes (64 halves + 8 pad)
#define MATB64 (128 * RS144)    // 18432 bytes per matrix
#define G_OFF_A 0
#define G_OFF_B (MATB64)
#define G_STAGE (2 * MATB64)    // 36864
#define G_NSTAGE 3
#define G_SMEM (G_NSTAGE * G_STAGE)  // 110592

DEV void issue64(unsigned sbs, const __half* __restrict__ A, const __half* __restrict__ Bm,
                 int K, int k0, int tid) {
#pragma unroll
    for (int i = 0; i < 4; i++) {
        int idx = tid + i * 256;
        int row = idx >> 3, g = idx & 7;
        cp16(sbs + G_OFF_A + row * RS144 + g * 16, A + (long)row * K + k0 + g * 8);
        cp16(sbs + G_OFF_B + row * RS144 + g * 16, Bm + (long)row * K + k0 + g * 8);
    }
    cp_commit();
}

// sel: 0 -> A=g_xgf (K=1024), B=g_iwf (N=4096), C=g_xzf
//      1 -> A=g_y2f (K=2048), B=g_owf (N=1024), C=g_ysf
__global__ void __launch_bounds__(256)
k_gemm_h(int sel, int N, int K) {
    int zi = blockIdx.z;
    int kk = zi >> 3, b = zi & 7;
    int z = b * 8 + kk;
    if (g_gw[z] == 0.f) return;

    const __half *A, *Bm;
    __half* C;
    if (sel == 0) {
        A  = g_xgf + (long)z * 256 * 1024;
        Bm = g_iwf + (long)kk * 4096 * 1024;
        C  = g_xzf + (long)z * 256 * 4096;
    } else {
        A  = g_y2f + (long)z * 256 * 2048;
        Bm = g_owf + (long)kk * 1024 * 2048;
        C  = g_ysf + (long)z * 256 * 1024;
    }

    int bm = blockIdx.y * 128, bn = blockIdx.x * 128;
    A  += (long)bm * K;
    Bm += (long)bn * K;

    extern __shared__ char dsm[];
    unsigned sb0 = smem_u32(dsm);
    int tid = threadIdx.x;
    int lane = tid & 31, warp = tid >> 5;
    int wm = (warp & 1) * 64, wn = (warp >> 1) * 32;
    int mi = lane >> 3, lr = lane & 7;
    int arow = (mi & 1) * 8 + lr;
    int akb  = (mi >> 1) * 16;
    int brow = (mi >> 1) * 8 + lr;
    int bkb  = (mi & 1) * 16;

    float acc[4][4][4];
#pragma unroll
    for (int i = 0; i < 4; i++)
#pragma unroll
        for (int j = 0; j < 4; j++)
#pragma unroll
            for (int r = 0; r < 4; r++) acc[i][j][r] = 0.f;

    int nk = K >> 6;

    issue64(sb0 + 0 * G_STAGE, A, Bm, K, 0, tid);
    issue64(sb0 + 1 * G_STAGE, A, Bm, K, 64, tid);
    cp_commit();   // empty pad group

    for (int j = 0; j < nk; j++) {
        cp_wait<2>();
        __syncthreads();
        if (j + 2 < nk) issue64(sb0 + ((j + 2) % 3) * G_STAGE, A, Bm, K, (j + 2) << 6, tid);
        else            cp_commit();
        unsigned sbs = sb0 + (j % 3) * G_STAGE;
#pragma unroll
        for (int ks = 0; ks < 4; ks++) {
            unsigned kb = ks * 32;
            unsigned ah[4][4];
#pragma unroll
            for (int mf = 0; mf < 4; mf++) {
                unsigned ro = (wm + mf * 16 + arow) * RS144 + kb + akb;
                ldmx4(ah[mf], sbs + G_OFF_A + ro);
            }
            unsigned bh[2][4];
#pragma unroll
            for (int p = 0; p < 2; p++) {
                unsigned ro = (wn + p * 16 + brow) * RS144 + kb + bkb;
                ldmx4(bh[p], sbs + G_OFF_B + ro);
            }
#pragma unroll
            for (int mf = 0; mf < 4; mf++)
#pragma unroll
                for (int nf = 0; nf < 4; nf++) {
                    const unsigned* bhp = &bh[nf >> 1][(nf & 1) * 2];
                    mma_f16(acc[mf][nf], ah[mf], bhp);
                }
        }
    }

    int g = lane >> 2, tI = lane & 3;
#pragma unroll
    for (int mf = 0; mf < 4; mf++) {
        int r0 = bm + wm + mf * 16 + g;
#pragma unroll
        for (int nf = 0; nf < 4; nf++) {
            int col = bn + wn + nf * 8 + tI * 2;
            *(__half2*)(C + (long)r0 * N + col)       = __floats2half2_rn(acc[mf][nf][0], acc[mf][nf][1]);
            *(__half2*)(C + (long)(r0 + 8) * N + col) = __floats2half2_rn(acc[mf][nf][2], acc[mf][nf][3]);
        }
    }
}

// ---------------- HMMA x_dbl GEMM (A fp16, B hi/lo 2-term) ------------------
#define RS80 80
#define MAT_B (128 * RS80)
#define X_OFF_A  0
#define X_OFF_BH (MAT_B)
#define X_OFF_BL (2 * MAT_B)
#define X_STAGE (3 * MAT_B)     // 30720
#define X_GSMEM (2 * X_STAGE)   // 61440

__global__ void __launch_bounds__(256)
k_gemm_xdbl_h() {
    int z = blockIdx.y;
    int kk = z & 7;
    if (g_gw[z] == 0.f) return;
    const int K = 2048;
    const __half* A  = g_uh + (long)z * 256 * 2048;
    const __half* Bh = g_xpwh + (long)kk * 96 * 2048;
    const __half* Bl = g_xpwl + (long)kk * 96 * 2048;
    float* C = g_xdbl + (long)z * 256 * 96;
    __half* Dh = g_xdh + (long)z * 256 * 64;

    int bm = blockIdx.x * 128;
    A += (long)bm * K;

    extern __shared__ char dsm[];
    unsigned sb0 = smem_u32(dsm);
    int tid = threadIdx.x;
    int lane = tid & 31, warp = tid >> 5;
    int wm = (warp & 1) * 64, wn = (warp >> 1) * 24;
    int mi = lane >> 3, lr = lane & 7;
    int arow = (mi & 1) * 8 + lr;
    int akb  = (mi >> 1) * 16;
    int brow = (mi >> 1) * 8 + lr;
    int bkb  = (mi & 1) * 16;

    float acc[4][3][4];
#pragma unroll
    for (int i = 0; i < 4; i++)
#pragma unroll
        for (int j = 0; j < 3; j++)
#pragma unroll
            for (int r = 0; r < 4; r++) acc[i][j][r] = 0.f;

    int ci0 = tid * 2;
    int row0 = ci0 >> 2, kc0 = (ci0 & 3);
    int row1 = (ci0 + 1) >> 2, kc1 = ((ci0 + 1) & 3);
    int rb0 = row0 < 96 ? row0 : 95;
    int rb1 = row1 < 96 ? row1 : 95;

#define XISSUE(J, BUF)                                                                       \
    {                                                                                        \
        int k0 = (J) << 5;                                                                   \
        unsigned sbs = sb0 + (BUF) * X_STAGE;                                                \
        cp16(sbs + X_OFF_A  + row0 * RS80 + kc0 * 16, A  + (long)row0 * K + k0 + kc0 * 8);   \
        cp16(sbs + X_OFF_A  + row1 * RS80 + kc1 * 16, A  + (long)row1 * K + k0 + kc1 * 8);   \
        cp16(sbs + X_OFF_BH + row0 * RS80 + kc0 * 16, Bh + (long)rb0 * K + k0 + kc0 * 8);    \
        cp16(sbs + X_OFF_BH + row1 * RS80 + kc1 * 16, Bh + (long)rb1 * K + k0 + kc1 * 8);    \
        cp16(sbs + X_OFF_BL + row0 * RS80 + kc0 * 16, Bl + (long)rb0 * K + k0 + kc0 * 8);    \
        cp16(sbs + X_OFF_BL + row1 * RS80 + kc1 * 16, Bl + (long)rb1 * K + k0 + kc1 * 8);    \
        cp_commit();                                                                         \
    }

    const int nk = 64;
    XISSUE(0, 0);
    for (int j = 0; j < nk; j++) {
        if (j + 1 < nk) { XISSUE(j + 1, (j + 1) & 1); cp_wait<1>(); }
        else            { cp_wait<0>(); }
        __syncthreads();
        unsigned sbs = sb0 + (j & 1) * X_STAGE;
#pragma unroll
        for (int ks = 0; ks < 2; ks++) {
            unsigned kb = ks * 32;
            unsigned ah[4][4];
#pragma unroll
            for (int mf = 0; mf < 4; mf++) {
                unsigned ro = (wm + mf * 16 + arow) * RS80 + kb + akb;
                ldmx4(ah[mf], sbs + X_OFF_A + ro);
            }
            unsigned bh[2][4], bl[2][4];
#pragma unroll
            for (int p = 0; p < 2; p++) {
                unsigned ro = (wn + p * 16 + brow) * RS80 + kb + bkb;
                ldmx4(bh[p], sbs + X_OFF_BH + ro);
                ldmx4(bl[p], sbs + X_OFF_BL + ro);
            }
#pragma unroll
            for (int mf = 0; mf < 4; mf++)
#pragma unroll
                for (int nf = 0; nf < 3; nf++) {
                    const unsigned* bhp = &bh[nf >> 1][(nf & 1) * 2];
                    const unsigned* blp = &bl[nf >> 1][(nf & 1) * 2];
                    mma_f16(acc[mf][nf], ah[mf], bhp);
                    mma_f16(acc[mf][nf], ah[mf], blp);
                }
        }
        __syncthreads();
    }

    int g = lane >> 2, tI = lane & 3;
#pragma unroll
    for (int mf = 0; mf < 4; mf++) {
        int r0 = bm + wm + mf * 16 + g;
#pragma unroll
        for (int nf = 0; nf < 3; nf++) {
            int col = wn + nf * 8 + tI * 2;
#pragma unroll
            for (int half = 0; half < 2; half++) {
                int r = r0 + half * 8;
                float v0 = acc[mf][nf][half * 2 + 0];
                float v1 = acc[mf][nf][half * 2 + 1];
                C[(long)r * 96 + col]     = v0;
                C[(long)r * 96 + col + 1] = v1;
                if (col < 64) {
                    Dh[(long)r * 64 + col]     = __float2half(v0);
                    Dh[(long)r * 64 + col + 1] = __float2half(v1);
                }
            }
        }
    }
}

// ---------------- HMMA dt GEMM (plain fp16, K=64, fp16 out) -----------------
#define D_OFF_A 0
#define D_OFF_B (MAT_B)
#define D_STAGE (2 * MAT_B)     // 20480
#define D_GSMEM (2 * D_STAGE)   // 40960

__global__ void __launch_bounds__(256)
k_gemm_dt_h(const float* __restrict__ bias) {
    int z = blockIdx.z;
    int kk = z & 7;
    if (g_gw[z] == 0.f) return;
    const int K = 64, N = 2048;
    const __half* A = g_xdh + (long)z * 256 * 64;
    const __half* B = g_dtwh + (long)kk * 2048 * 64;
    __half* C = g_dtf + (long)z * 256 * 2048;

    int bm = blockIdx.y * 128, bn = blockIdx.x * 128;
    A += (long)bm * K;
    B += (long)bn * K;

    extern __shared__ char dsm[];
    unsigned sb0 = smem_u32(dsm);
    int tid = threadIdx.x;
    int lane = tid & 31, warp = tid >> 5;
    int wm = (warp & 1) * 64, wn = (warp >> 1) * 32;
    int mi = lane >> 3, lr = lane & 7;
    int arow = (mi & 1) * 8 + lr;
    int akb  = (mi >> 1) * 16;
    int brow = (mi >> 1) * 8 + lr;
    int bkb  = (mi & 1) * 16;

    float acc[4][4][4];
#pragma unroll
    for (int i = 0; i < 4; i++)
#pragma unroll
        for (int j = 0; j < 4; j++)
#pragma unroll
            for (int r = 0; r < 4; r++) acc[i][j][r] = 0.f;

    int ci0 = tid * 2;
    int row0 = ci0 >> 2, kc0 = (ci0 & 3);
    int row1 = (ci0 + 1) >> 2, kc1 = ((ci0 + 1) & 3);

#define DISSUE(J, BUF)                                                                      \
    {                                                                                       \
        int k0 = (J) << 5;                                                                  \
        unsigned sbs = sb0 + (BUF) * D_STAGE;                                               \
        cp16(sbs + D_OFF_A + row0 * RS80 + kc0 * 16, A + (long)row0 * K + k0 + kc0 * 8);    \
        cp16(sbs + D_OFF_A + row1 * RS80 + kc1 * 16, A + (long)row1 * K + k0 + kc1 * 8);    \
        cp16(sbs + D_OFF_B + row0 * RS80 + kc0 * 16, B + (long)row0 * K + k0 + kc0 * 8);    \
        cp16(sbs + D_OFF_B + row1 * RS80 + kc1 * 16, B + (long)row1 * K + k0 + kc1 * 8);    \
        cp_commit();                                                                        \
    }

    DISSUE(0, 0);
    DISSUE(1, 1);
    cp_wait<0>();
    __syncthreads();

#pragma unroll
    for (int j = 0; j < 2; j++) {
        unsigned sbs = sb0 + j * D_STAGE;
#pragma unroll
        for (int ks = 0; ks < 2; ks++) {
            unsigned kb = ks * 32;
            unsigned ah[4][4];
#pragma unroll
            for (int mf = 0; mf < 4; mf++) {
                unsigned ro = (wm + mf * 16 + arow) * RS80 + kb + akb;
                ldmx4(ah[mf], sbs + D_OFF_A + ro);
            }
            unsigned bh[2][4];
#pragma unroll
            for (int p = 0; p < 2; p++) {
                unsigned ro = (wn + p * 16 + brow) * RS80 + kb + bkb;
                ldmx4(bh[p], sbs + D_OFF_B + ro);
            }
#pragma unroll
            for (int mf = 0; mf < 4; mf++)
#pragma unroll
                for (int nf = 0; nf < 4; nf++) {
                    const unsigned* bhp = &bh[nf >> 1][(nf & 1) * 2];
                    mma_f16(acc[mf][nf], ah[mf], bhp);
                }
        }
    }

    int g = lane >> 2, tI = lane & 3;
#pragma unroll
    for (int mf = 0; mf < 4; mf++) {
        int r0 = bm + wm + mf * 16 + g;
#pragma unroll
        for (int nf = 0; nf < 4; nf++) {
            int col = bn + wn + nf * 8 + tI * 2;
            float b0 = bias[kk * N + col], b1 = bias[kk * N + col + 1];
#pragma unroll
            for (int half = 0; half < 2; half++) {
                int r = r0 + half * 8;
                float v0 = acc[mf][nf][half * 2 + 0] + b0;
                float v1 = acc[mf][nf][half * 2 + 1] + b1;
                v0 = (v0 > 20.f) ? v0 : log1pf(__expf(v0));
                v1 = (v1 > 20.f) ? v1 : log1pf(__expf(v1));
                C[(long)r * N + col]     = __float2half(v0);
                C[(long)r * N + col + 1] = __float2half(v1);
            }
        }
    }
}

// ---------------- depthwise causal conv (l-parallel, fp16 in/out) -----------
__global__ void k_conv(const float* __restrict__ cw, const float* __restrict__ cb) {
    int gb = blockIdx.x;
    int l = gb & 255, z = gb >> 8;
    int k = z & 7;
    if (g_gw[z] == 0.f) return;
    const __half* xzb = g_xzf + (long)z * 256 * 4096;
    long ubase = ((long)z * 256 + l) * 2048;
#pragma unroll
    for (int i = 0; i < 8; i++) {
        int d = threadIdx.x + i * 256;
        float4 w4 = ((const float4*)cw)[k * 2048 + d];
        float acc = cb[k * 2048 + d];
        float wv[4] = {w4.x, w4.y, w4.z, w4.w};
#pragma unroll
        for (int j = 0; j < 4; j++) {
            int lp = l - 3 + j;
            if (lp >= 0) acc += wv[j] * __half2float(xzb[(long)lp * 4096 + d]);
        }
        float u = acc / (1.f + __expf(-acc));  // silu
        g_uh[ubase + d] = __float2half(u);
    }
}

// ---------------- selective scan -> y2 fp16 ---------------------------------
__global__ void k_scan(const float* __restrict__ A_log, const float* __restrict__ D_p) {
    __shared__ float sbc[256 * 32];
    int gb = blockIdx.x;
    int z = gb >> 3, dblk = gb & 7;
    int k = z & 7;
    if (g_gw[z] == 0.f) return;
    for (int idx = threadIdx.x; idx < 8192; idx += 256)
        sbc[idx] = g_xdbl[((long)z * 256 + (idx >> 5)) * 96 + 64 + (idx & 31)];
    __syncthreads();
    int d = dblk * 256 + threadIdx.x;
    float a[16];
#pragma unroll
    for (int s = 0; s < 16; s++) a[s] = -__expf(A_log[(long)(k * 2048 + d) * 16 + s]);
    bool fast = true;
#pragma unroll
    for (int s = 0; s < 16; s++) {
        float r = a[s] / a[0];
        if (fabsf(r - (float)(s + 1)) > 1e-4f) fast = false;
    }
    float dp = D_p[k * 2048 + d];
    float h[16];
#pragma unroll
    for (int s = 0; s < 16; s++) h[s] = 0.f;
    const __half* dtb = g_dtf + (long)z * 256 * 2048 + d;
    const __half* uhb = g_uh + (long)z * 256 * 2048 + d;
    const __half* zb  = g_xzf + (long)z * 256 * 4096 + 2048 + d;
    long ybase = (long)z * 256 * 2048 + d;
    for (int l = 0; l < 256; l++) {
        float dt = __half2float(dtb[(long)l * 2048]);
        float uu = __half2float(uhb[(long)l * 2048]);
        float zz = __half2float(zb[(long)l * 4096]);
        float dtu = dt * uu;
        float acc = 0.f;
        const float* bc = &sbc[l * 32];
        if (fast) {
            float e = __expf(dt * a[0]);
            float p = 1.f;
#pragma unroll
            for (int s = 0; s < 16; s++) {
                p *= e;
                h[s] = p * h[s] + dtu * bc[s];
                acc += h[s] * bc[16 + s];
            }
        } else {
#pragma unroll
            for (int s = 0; s < 16; s++) {
                float e = __expf(dt * a[s]);
                h[s] = e * h[s] + dtu * bc[s];
                acc += h[s] * bc[16 + s];
            }
        }
        float y = acc + uu * dp;
        y *= zz / (1.f + __expf(-zz));  // * silu(z)
        g_y2f[ybase + (long)l * 2048] = __float2half(y);
    }
}

// ---------------- cross-merge (2 outputs/thread, __half2 gathers) -----------
__global__ void k_merge(float* __restrict__ out) {
    int t = blockIdx.x * 256 + threadIdx.x;     // 1,048,576 threads, 2 outputs each
    int pix = t & 255, c2 = (t >> 8) & 511, b = t >> 17;
    int c = c2 * 2;
    int h = pix >> 4, w = pix & 15;
    int l0 = pix;
    int l1 = w * 16 + h;
    int ld = ((w - h) & 15) * 16 + h;
    int la = ((w + h) & 15) * 16 + h;
    int pos[8] = {l0, l1, 255 - l0, 255 - l1, ld, la, 255 - ld, 255 - la};
    float a0 = 0.f, a1 = 0.f;
#pragma unroll
    for (int k = 0; k < 8; k++) {
        float g = g_gw[b * 8 + k];
        if (g != 0.f) {
            __half2 v = *(const __half2*)&g_ysf[((long)(b * 8 + k) * 256 + pos[k]) * 1024 + c];
            float2 f = __half22float2(v);
            a0 += g * f.x;
            a1 += g * f.y;
        }
    }
    *(float2*)&out[((long)b * 1024 + c) * 256 + pix * 0 + 0] = make_float2(0.f, 0.f);  // placeholder avoided below
}

// NOTE: out layout is (b, c, pix) flattened as b*1024*256 + c*256 + pix — the two
// outputs for (c, c+1) are NOT adjacent. Use scalar stores.
__global__ void k_merge2(float* __restrict__ out) {
    int t = blockIdx.x * 256 + threadIdx.x;     // 1,048,576 threads, 2 outputs each
    int pix = t & 255, c2 = (t >> 8) & 511, b = t >> 17;
    int c = c2 * 2;
    int h = pix >> 4, w = pix & 15;
    int l0 = pix;
    int l1 = w * 16 + h;
    int ld = ((w - h) & 15) * 16 + h;
    int la = ((w + h) & 15) * 16 + h;
    int pos[8] = {l0, l1, 255 - l0, 255 - l1, ld, la, 255 - ld, 255 - la};
    float a0 = 0.f, a1 = 0.f;
#pragma unroll
    for (int k = 0; k < 8; k++) {
        float g = g_gw[b * 8 + k];
        if (g != 0.f) {
            __half2 v = *(const __half2*)&g_ysf[((long)(b * 8 + k) * 256 + pos[k]) * 1024 + c];
            float2 f = __half22float2(v);
            a0 += g * f.x;
            a1 += g * f.y;
        }
    }
    long ob = (long)b * 1024 * 256 + pix;
    out[ob + (long)c * 256]       = a0;
    out[ob + (long)(c + 1) * 256] = a1;
}

// ---------------- launch ----------------
extern "C" void kernel_launch(void* const* d_in, const int* in_sizes, int n_in,
                              void* d_out, int out_size) {
    const float* x        = (const float*)d_in[0];
    const float* pw       = (const float*)d_in[1];
    const float* bn_g     = (const float*)d_in[2];
    const float* bn_b     = (const float*)d_in[3];
    const float* gate_w   = (const float*)d_in[4];
    const float* ln_g     = (const float*)d_in[5];
    const float* ln_b     = (const float*)d_in[6];
    const float* fd_scale = (const float*)d_in[7];
    const float* in_w     = (const float*)d_in[8];
    const float* cw       = (const float*)d_in[9];
    const float* cb       = (const float*)d_in[10];
    const float* xp_w     = (const float*)d_in[11];
    const float* dtp_w    = (const float*)d_in[12];
    const float* dtp_b    = (const float*)d_in[13];
    const float* A_log    = (const float*)d_in[14];
    const float* D_p      = (const float*)d_in[15];
    const float* out_w    = (const float*)d_in[16];
    float* out = (float*)d_out;

    cudaFuncSetAttribute(k_gemm_h, cudaFuncAttributeMaxDynamicSharedMemorySize, G_SMEM);
    cudaFuncSetAttribute(k_gemm_xdbl_h, cudaFuncAttributeMaxDynamicSharedMemorySize, X_GSMEM);
    cudaFuncSetAttribute(k_gemm_dt_h, cudaFuncAttributeMaxDynamicSharedMemorySize, D_GSMEM);

    // fused weight conversions (one launch)
    {
        long blocks = (SP_TOT + 255) / 256;
        k_split_all<<<(unsigned)blocks, 256>>>((const float4*)in_w, (const float4*)out_w,
                                               xp_w, dtp_w);
    }

    k_pool<<<8 * 512, 288>>>(x);
    k_cbr_gemm<<<8 * 8, 256>>>(x, 1, 0,   256, 0, pw, bn_g, bn_b, 8);   // p0 map
    k_cbr_gemm<<<8 * 1, 256>>>(x, 0, 0,    25, 1, pw, bn_g, bn_b, 1);   // s=5
    k_cbr_gemm<<<8 * 3, 256>>>(x, 0, 25,   81, 2, pw, bn_g, bn_b, 3);   // s=9
    k_cbr_gemm<<<8 * 6, 256>>>(x, 0, 106, 169, 3, pw, bn_g, bn_b, 6);   // s=13
    k_p0_reduce<<<8 * 128, 256>>>();
    k_assemble<<<8 * 256, 256>>>(x);
    k_gate_weights<<<8, 1024>>>(gate_w);
    k_fdgate<<<8 * 8 * 256, 256>>>(ln_g, ln_b, fd_scale);

    // in_proj (fp16 HMMA, K-chunk 64, fp16 out)
    { dim3 g(32, 2, 64); k_gemm_h<<<g, 256, G_SMEM>>>(0, 4096, 1024); }
    // depthwise conv + silu -> u fp16 (l-parallel)
    k_conv<<<64 * 256, 256>>>(cw, cb);
    // x_dbl (HMMA, A fp16 + B hi/lo 2-term)
    { dim3 g(2, 64); k_gemm_xdbl_h<<<g, 256, X_GSMEM>>>(); }
    // dt projection + softplus (plain fp16 HMMA)
    { dim3 g(16, 2, 64); k_gemm_dt_h<<<g, 256, D_GSMEM>>>(dtp_b); }
    // selective scan
    k_scan<<<64 * 8, 256>>>(A_log, D_p);
    // out_proj (fp16 HMMA, K-chunk 64, fp16 out)
    { dim3 g(8, 2, 64); k_gemm_h<<<g, 256, G_SMEM>>>(1, 1024, 2048); }
    // cross-merge (2 outputs/thread)
    k_merge2<<<4096, 256>>>(out);
}

// round 16
// speedup vs baseline: 1.2151x; 1.1198x over previous
#include <cuda_runtime.h>
#include <cuda_bf16.h>
#include <cuda_fp16.h>
#include <cstdint>
#include <math.h>

#define DEV __device__ __forceinline__

// ---------------- problem constants ----------------
// B=8, C=512, H=W=16, L=256, dim=128, chs=1024
// d_inner=2048, d_state=16, d_conv=4, dt_rank=64, 8 branches

// ---------------- scratch (device globals) ----------
__device__ float g_pool[8 * 512 * 275];
__device__ float g_cbr [8 * 128 * 275];
__device__ float g_p0map[8 * 128 * 256];
__device__ float g_p0  [8 * 128];
__device__ float g_xcT [8 * 256 * 1024];
__device__ float g_gw  [64];
__device__ float g_xdbl[8 * 8 * 256 * 96];         // x_proj output fp32 (B,C used by scan)

// fp16 operands / intermediates
__device__ __half g_xzf[8 * 8 * 256 * 4096];       // in_proj output (u|z) fp16
__device__ __half g_ysf[8 * 8 * 256 * 1024];       // out_proj output fp16
__device__ __half g_dtf[8 * 8 * 256 * 2048];       // softplus(dt) fp16
__device__ __half g_xgf[8 * 8 * 256 * 1024];       // fdgate out (single fp16)
__device__ __half g_y2f[8 * 8 * 256 * 2048];       // scan out (single fp16)
__device__ __half g_iwf[8 * 4096 * 1024];          // in_w fp16
__device__ __half g_owf[8 * 1024 * 2048];          // out_w fp16
__device__ __half g_uh [8 * 8 * 256 * 2048];       // u fp16 (single)
__device__ __half g_xpwh[8 * 96 * 2048];           // xp_w hi
__device__ __half g_xpwl[8 * 96 * 2048];           // xp_w lo
__device__ __half g_dtwh[8 * 2048 * 64];           // dtp_w fp16
__device__ __half g_xdh[8 * 8 * 256 * 64];         // xdbl[:, :64] fp16 (compact)

// ---------------- helpers ----------------
DEV float block_sum(float v, float* red) {
    int lane = threadIdx.x & 31, wid = threadIdx.x >> 5;
#pragma unroll
    for (int o = 16; o > 0; o >>= 1) v += __shfl_xor_sync(0xffffffffu, v, o);
    if (lane == 0) red[wid] = v;
    __syncthreads();
    if (wid == 0) {
        float w = (lane < 8) ? red[lane] : 0.f;
#pragma unroll
        for (int o = 4; o > 0; o >>= 1) w += __shfl_xor_sync(0xffffffffu, w, o);
        if (lane == 0) red[0] = w;
    }
    __syncthreads();
    float r = red[0];
    __syncthreads();
    return r;
}

// fused two-value block sum (8 warps): a -> red[0], b -> red[1]
DEV void block_sum2(float& a, float& b, float* red) {
    int lane = threadIdx.x & 31, wid = threadIdx.x >> 5;
#pragma unroll
    for (int o = 16; o > 0; o >>= 1) {
        a += __shfl_xor_sync(0xffffffffu, a, o);
        b += __shfl_xor_sync(0xffffffffu, b, o);
    }
    if (lane == 0) { red[wid] = a; red[8 + wid] = b; }
    __syncthreads();
    if (wid == 0) {
        float w = (lane < 16) ? red[lane] : 0.f;
#pragma unroll
        for (int o = 4; o > 0; o >>= 1) w += __shfl_xor_sync(0xffffffffu, w, o);
        if (lane == 0) red[0] = w;
        if (lane == 8) red[1] = w;
    }
    __syncthreads();
    a = red[0];
    b = red[1];
    __syncthreads();
}

DEV int pix_of(int k, int l) {
    int p = (k == 2 || k == 3 || k == 6 || k == 7) ? (255 - l) : l;
    switch (k) {
        case 0: case 2: return p;
        case 1: case 3: { int w = p >> 4, h = p & 15; return h * 16 + w; }
        case 4: case 6: { int wp = p >> 4, h = p & 15; int w = (h + wp) & 15; return h * 16 + w; }
        default:        { int wp = p >> 4, h = p & 15; int w = (wp - h) & 15; return h * 16 + w; }
    }
}

DEV void split_h(float v, __half& h, __half& l) {
    h = __float2half(v);
    l = __float2half(v - __half2float(h));
}

DEV unsigned smem_u32(const void* p) {
    unsigned a;
    asm("{ .reg .u64 t; cvta.to.shared.u64 t, %1; cvt.u32.u64 %0, t; }" : "=r"(a) : "l"(p));
    return a;
}

DEV void cp16(unsigned dst, const void* src) {
    asm volatile("cp.async.cg.shared.global [%0], [%1], 16;" :: "r"(dst), "l"(src));
}
DEV void cp_commit() { asm volatile("cp.async.commit_group;" ::: "memory"); }
template <int N> DEV void cp_wait() { asm volatile("cp.async.wait_group %0;" :: "n"(N) : "memory"); }

DEV void ldmx4(unsigned* r, unsigned addr) {
    asm volatile("ldmatrix.sync.aligned.m8n8.x4.shared.b16 {%0,%1,%2,%3}, [%4];"
                 : "=r"(r[0]), "=r"(r[1]), "=r"(r[2]), "=r"(r[3]) : "r"(addr));
}
DEV void mma_f16(float* d, const unsigned* a, const unsigned* b) {
    asm volatile(
        "mma.sync.aligned.m16n8k16.row.col.f32.f16.f16.f32 "
        "{%0,%1,%2,%3}, {%4,%5,%6,%7}, {%8,%9}, {%0,%1,%2,%3};"
        : "+f"(d[0]), "+f"(d[1]), "+f"(d[2]), "+f"(d[3])
        : "r"(a[0]), "r"(a[1]), "r"(a[2]), "r"(a[3]), "r"(b[0]), "r"(b[1]));
}

// ---------------- stage 1: pyramid pooling ----------------
__global__ void k_pool(const float* __restrict__ x) {
    __shared__ float sx[256];
    int b = blockIdx.x / 512, c = blockIdx.x % 512;
    const float* xp = x + (b * 512 + c) * 256;
    for (int i = threadIdx.x; i < 256; i += blockDim.x) sx[i] = xp[i];
    __syncthreads();
    int t = threadIdx.x;
    if (t < 275) {
        int s, idx;
        if (t < 25)       { s = 5;  idx = t; }
        else if (t < 106) { s = 9;  idx = t - 25; }
        else              { s = 13; idx = t - 106; }
        int i = idx / s, j = idx % s;
        int r0 = i * 16 / s, r1 = ((i + 1) * 16 + s - 1) / s;
        int c0 = j * 16 / s, c1 = ((j + 1) * 16 + s - 1) / s;
        float sum = 0.f;
        for (int r = r0; r < r1; r++)
            for (int cc = c0; cc < c1; cc++) sum += sx[r * 16 + cc];
        g_pool[(b * 512 + c) * 275 + t] = sum / (float)((r1 - r0) * (c1 - c0));
    }
}

// ---------------- fused CBR (all 4 variants in ONE launch) -------------------
// block decode: [0,64) p0-map (useX) ; [64,72) s=5 ; [72,96) s=9 ; [96,144) s=13
__global__ void __launch_bounds__(256)
k_cbr_all(const float* __restrict__ x, const float* __restrict__ pw,
          const float* __restrict__ bn_g, const float* __restrict__ bn_b) {
    int bid = blockIdx.x;
    int useX, off, posCnt, scale, b, tile;
    if (bid < 64)       { useX = 1; off = 0;   posCnt = 256; scale = 0; b = bid >> 3;        tile = bid & 7; }
    else if (bid < 72)  { useX = 0; off = 0;   posCnt = 25;  scale = 1; b = bid - 64;        tile = 0; }
    else if (bid < 96)  { useX = 0; off = 25;  posCnt = 81;  scale = 2; b = (bid - 72) / 3;  tile = (bid - 72) % 3; }
    else                { useX = 0; off = 106; posCnt = 169; scale = 3; b = (bid - 96) / 6;  tile = (bid - 96) % 6; }
    int pos0 = tile * 32;
    if (pos0 >= posCnt) return;
    __shared__ float ws[128][33];
    __shared__ float ps[32][33];
    int tid = threadIdx.x, lane = tid & 31, warp = tid >> 5;
    int tx = tid & 7, ty = tid >> 3;
    int ldS = useX ? 256 : 275;
    const float* src = useX ? x : (const float*)g_pool;
    float acc[4][4];
#pragma unroll
    for (int i = 0; i < 4; i++)
#pragma unroll
        for (int j = 0; j < 4; j++) acc[i][j] = 0.f;

    for (int k0 = 0; k0 < 512; k0 += 32) {
#pragma unroll
        for (int i = 0; i < 16; i++) {
            int o = warp * 16 + i;
            ws[o][lane] = pw[(long)(scale * 128 + o) * 512 + k0 + lane];
        }
#pragma unroll
        for (int i = 0; i < 4; i++) {
            int kc = warp * 4 + i, c = k0 + kc;
            int p = pos0 + lane;
            ps[kc][lane] = (p < posCnt) ? src[((long)b * 512 + c) * ldS + off + p] : 0.f;
        }
        __syncthreads();
#pragma unroll
        for (int kc = 0; kc < 32; kc++) {
            float a0 = ws[ty * 4 + 0][kc], a1 = ws[ty * 4 + 1][kc];
            float a2 = ws[ty * 4 + 2][kc], a3 = ws[ty * 4 + 3][kc];
            float p0 = ps[kc][tx * 4 + 0], p1 = ps[kc][tx * 4 + 1];
            float p2 = ps[kc][tx * 4 + 2], p3 = ps[kc][tx * 4 + 3];
            acc[0][0] += a0 * p0; acc[0][1] += a0 * p1; acc[0][2] += a0 * p2; acc[0][3] += a0 * p3;
            acc[1][0] += a1 * p0; acc[1][1] += a1 * p1; acc[1][2] += a1 * p2; acc[1][3] += a1 * p3;
            acc[2][0] += a2 * p0; acc[2][1] += a2 * p1; acc[2][2] += a2 * p2; acc[2][3] += a2 * p3;
            acc[3][0] += a3 * p0; acc[3][1] += a3 * p1; acc[3][2] += a3 * p2; acc[3][3] += a3 * p3;
        }
        __syncthreads();
    }
    float gsc = rsqrtf(1.f + 1e-5f);
#pragma unroll
    for (int i = 0; i < 4; i++) {
        int o = ty * 4 + i;
        float g = bn_g[scale * 128 + o] * gsc;
        float bb = bn_b[scale * 128 + o];
#pragma unroll
        for (int j = 0; j < 4; j++) {
            int p = pos0 + tx * 4 + j;
            if (p < posCnt) {
                float v = fminf(fmaxf(acc[i][j] * g + bb, 0.f), 6.f);
                if (useX) g_p0map[((long)b * 128 + o) * 256 + p] = v;
                else      g_cbr [((long)b * 128 + o) * 275 + off + p] = v;
            }
        }
    }
}

__global__ void k_p0_reduce() {
    int b = blockIdx.x >> 7, o = blockIdx.x & 127;
    __shared__ float red[256];
    int p = threadIdx.x;
    red[p] = g_p0map[((long)b * 128 + o) * 256 + p];
    __syncthreads();
    for (int st = 128; st > 0; st >>= 1) { if (p < st) red[p] += red[p + st]; __syncthreads(); }
    if (p == 0) g_p0[b * 128 + o] = red[0] * (1.f / 256.f);
}

__global__ void k_assemble(const float* __restrict__ x) {
    int b = blockIdx.x / 256, pix = blockIdx.x % 256;
    int h = pix / 16, w = pix % 16;
    float* out = g_xcT + (b * 256 + pix) * 1024;
    for (int i = 0; i < 4; i++) {
        int c = threadIdx.x + i * 256;
        float v;
        if (c < 128) {
            v = g_p0[b * 128 + c];
        } else if (c < 512) {
            int sc = (c - 128) / 128, o = (c - 128) % 128;
            int s   = sc == 0 ? 5 : (sc == 1 ? 9 : 13);
            int off = sc == 0 ? 0 : (sc == 1 ? 25 : 106);
            float fy = (h + 0.5f) * s * (1.f / 16.f) - 0.5f;
            float fx = (w + 0.5f) * s * (1.f / 16.f) - 0.5f;
            int y0 = (int)floorf(fy), x0 = (int)floorf(fx);
            float wy = fy - y0, wx = fx - x0;
            int y1 = min(y0 + 1, s - 1), x1 = min(x0 + 1, s - 1);
            y0 = max(y0, 0); x0 = max(x0, 0);
            const float* base = g_cbr + (b * 128 + o) * 275 + off;
            float v00 = base[y0 * s + x0], v01 = base[y0 * s + x1];
            float v10 = base[y1 * s + x0], v11 = base[y1 * s + x1];
            v = v00 * (1 - wy) * (1 - wx) + v01 * (1 - wy) * wx
              + v10 * wy * (1 - wx) + v11 * wy * wx;
        } else {
            v = x[(b * 512 + (c - 512)) * 256 + pix];
        }
        out[c] = v;
    }
}

// ---------------- stage 2: gate weights (softmax + top4) ----------------
__global__ void k_gate_weights(const float* __restrict__ gate_w) {
    __shared__ float sm[1024];
    __shared__ float slog[8];
    int b = blockIdx.x, t = threadIdx.x;
    float s = 0.f;
    const float* base = g_xcT + b * 256 * 1024;
    for (int p = 0; p < 256; p++) s += base[p * 1024 + t];
    sm[t] = s * (1.f / 256.f);
    __syncthreads();
    if (t < 256) {
        int k = t / 32, lane = t % 32;
        float acc = 0.f;
        for (int c = lane; c < 1024; c += 32) acc += sm[c] * gate_w[k * 1024 + c];
#pragma unroll
        for (int o = 16; o > 0; o >>= 1) acc += __shfl_down_sync(0xffffffffu, acc, o);
        if (lane == 0) slog[k] = acc;
    }
    __syncthreads();
    if (t == 0) {
        float mx = -1e30f;
        for (int k = 0; k < 8; k++) mx = fmaxf(mx, slog[k]);
        float e[8], se = 0.f;
        for (int k = 0; k < 8; k++) { e[k] = expf(slog[k] - mx); se += e[k]; }
        float sc[8];
        for (int k = 0; k < 8; k++) sc[k] = e[k] / se;
        float gwv[8];
        bool used[8];
        for (int k = 0; k < 8; k++) { gwv[k] = 0.f; used[k] = false; }
        for (int r = 0; r < 4; r++) {
            int bi = -1; float bv = -1e30f;
            for (int k = 0; k < 8; k++)
                if (!used[k] && sc[k] > bv) { bv = sc[k]; bi = k; }
            used[bi] = true; gwv[bi] = bv;
        }
        for (int k = 0; k < 8; k++) g_gw[b * 8 + k] = gwv[k];
    }
}

// ---------------- stage 3: cross-scan + fd_gate -> xg (fp16) ---------------
__global__ void k_fdgate(const float* __restrict__ ln_g, const float* __restrict__ ln_b,
                         const float* __restrict__ fd_scale) {
    int z = blockIdx.x;
    int l = z & 255, k = (z >> 8) & 7, b = z >> 11;
    if (g_gw[b * 8 + k] == 0.f) return;
    int pix = pix_of(k, l);
    int pixp = (l > 0) ? pix_of(k, l - 1) : -1;
    const float* cur = g_xcT + (b * 256 + pix) * 1024;
    const float* prv = (pixp >= 0) ? g_xcT + (b * 256 + pixp) * 1024 : nullptr;
    __shared__ float red[32];
    int t = threadIdx.x;
    float xv[4], dv[4];
    float s1 = 0.f, s2 = 0.f;
#pragma unroll
    for (int i = 0; i < 4; i++) {
        int c = t + i * 256;
        xv[i] = cur[c];
        float pvv = prv ? prv[c] : 0.f;
        dv[i] = xv[i] - pvv;
        s1 += dv[i];
        s2 += dv[i] * dv[i];
    }
    block_sum2(s1, s2, red);
    float mu = s1 * (1.f / 1024.f);
    float var = s2 * (1.f / 1024.f) - mu * mu;
    float rstd = rsqrtf(var + 1e-5f);
    float s3 = 0.f;
#pragma unroll
    for (int i = 0; i < 4; i++) {
        int c = t + i * 256;
        float dn = (dv[i] - mu) * rstd * ln_g[c] + ln_b[c];
        s3 += dn * dn;
    }
    float S3 = block_sum(s3, red);
    float nd = sqrtf(S3) * fd_scale[0];
    float gate = 0.2f + 0.8f * tanhf(fabsf(nd));
    long rowoff = ((long)(b * 8 + k) * 256 + l) * 1024;
#pragma unroll
    for (int i = 0; i < 4; i++) {
        int c = t + i * 256;
        g_xgf[rowoff + c] = __float2half(xv[i] * gate);
    }
}

// ---------------- fused weight conversions (one launch) ---------------------
#define SP_N1 (8L * 4096 * 1024 / 4)
#define SP_N2 (8L * 1024 * 2048 / 4)
#define SP_N3 (8L * 96 * 2048)
#define SP_N4 (8L * 2048 * 64)
#define SP_TOT (SP_N1 + SP_N2 + SP_N3 + SP_N4)

__global__ void k_split_all(const float4* __restrict__ in_w, const float4* __restrict__ out_w,
                            const float* __restrict__ xp_w, const float* __restrict__ dtp_w) {
    long i = (long)blockIdx.x * 256 + threadIdx.x;
    if (i < SP_N1) {
        float4 v = in_w[i];
        __half2* dst = (__half2*)g_iwf;
        dst[i * 2]     = __floats2half2_rn(v.x, v.y);
        dst[i * 2 + 1] = __floats2half2_rn(v.z, v.w);
    } else if (i < SP_N1 + SP_N2) {
        long j = i - SP_N1;
        float4 v = out_w[j];
        __half2* dst = (__half2*)g_owf;
        dst[j * 2]     = __floats2half2_rn(v.x, v.y);
        dst[j * 2 + 1] = __floats2half2_rn(v.z, v.w);
    } else if (i < SP_N1 + SP_N2 + SP_N3) {
        long j = i - SP_N1 - SP_N2;
        __half h, l;
        split_h(xp_w[j], h, l);
        g_xpwh[j] = h;
        g_xpwl[j] = l;
    } else if (i < SP_TOT) {
        long j = i - SP_N1 - SP_N2 - SP_N3;
        g_dtwh[j] = __float2half(dtp_w[j]);
    }
}

// ---------------- fp16 HMMA GEMM (K-chunk 64, 3-stage ring, fp16 out) -------
#define RS144 144               // row stride bytes (64 halves + 8 pad)
#define MATB64 (128 * RS144)    // 18432 bytes per matrix
#define G_OFF_A 0
#define G_OFF_B (MATB64)
#define G_STAGE (2 * MATB64)    // 36864
#define G_NSTAGE 3
#define G_SMEM (G_NSTAGE * G_STAGE)  // 110592

DEV void issue64(unsigned sbs, const __half* __restrict__ A, const __half* __restrict__ Bm,
                 int K, int k0, int tid) {
#pragma unroll
    for (int i = 0; i < 4; i++) {
        int idx = tid + i * 256;
        int row = idx >> 3, g = idx & 7;
        cp16(sbs + G_OFF_A + row * RS144 + g * 16, A + (long)row * K + k0 + g * 8);
        cp16(sbs + G_OFF_B + row * RS144 + g * 16, Bm + (long)row * K + k0 + g * 8);
    }
    cp_commit();
}

// sel: 0 -> A=g_xgf (K=1024), B=g_iwf (N=4096), C=g_xzf
//      1 -> A=g_y2f (K=2048), B=g_owf (N=1024), C=g_ysf
__global__ void __launch_bounds__(256)
k_gemm_h(int sel, int N, int K) {
    int zi = blockIdx.z;
    int kk = zi >> 3, b = zi & 7;
    int z = b * 8 + kk;
    if (g_gw[z] == 0.f) return;

    const __half *A, *Bm;
    __half* C;
    if (sel == 0) {
        A  = g_xgf + (long)z * 256 * 1024;
        Bm = g_iwf + (long)kk * 4096 * 1024;
        C  = g_xzf + (long)z * 256 * 4096;
    } else {
        A  = g_y2f + (long)z * 256 * 2048;
        Bm = g_owf + (long)kk * 1024 * 2048;
        C  = g_ysf + (long)z * 256 * 1024;
    }

    int bm = blockIdx.y * 128, bn = blockIdx.x * 128;
    A  += (long)bm * K;
    Bm += (long)bn * K;

    extern __shared__ char dsm[];
    unsigned sb0 = smem_u32(dsm);
    int tid = threadIdx.x;
    int lane = tid & 31, warp = tid >> 5;
    int wm = (warp & 1) * 64, wn = (warp >> 1) * 32;
    int mi = lane >> 3, lr = lane & 7;
    int arow = (mi & 1) * 8 + lr;
    int akb  = (mi >> 1) * 16;
    int brow = (mi >> 1) * 8 + lr;
    int bkb  = (mi & 1) * 16;

    float acc[4][4][4];
#pragma unroll
    for (int i = 0; i < 4; i++)
#pragma unroll
        for (int j = 0; j < 4; j++)
#pragma unroll
            for (int r = 0; r < 4; r++) acc[i][j][r] = 0.f;

    int nk = K >> 6;

    issue64(sb0 + 0 * G_STAGE, A, Bm, K, 0, tid);
    issue64(sb0 + 1 * G_STAGE, A, Bm, K, 64, tid);
    cp_commit();   // empty pad group

    for (int j = 0; j < nk; j++) {
        cp_wait<2>();
        __syncthreads();
        if (j + 2 < nk) issue64(sb0 + ((j + 2) % 3) * G_STAGE, A, Bm, K, (j + 2) << 6, tid);
        else            cp_commit();
        unsigned sbs = sb0 + (j % 3) * G_STAGE;
#pragma unroll
        for (int ks = 0; ks < 4; ks++) {
            unsigned kb = ks * 32;
            unsigned ah[4][4];
#pragma unroll
            for (int mf = 0; mf < 4; mf++) {
                unsigned ro = (wm + mf * 16 + arow) * RS144 + kb + akb;
                ldmx4(ah[mf], sbs + G_OFF_A + ro);
            }
            unsigned bh[2][4];
#pragma unroll
            for (int p = 0; p < 2; p++) {
                unsigned ro = (wn + p * 16 + brow) * RS144 + kb + bkb;
                ldmx4(bh[p], sbs + G_OFF_B + ro);
            }
#pragma unroll
            for (int mf = 0; mf < 4; mf++)
#pragma unroll
                for (int nf = 0; nf < 4; nf++) {
                    const unsigned* bhp = &bh[nf >> 1][(nf & 1) * 2];
                    mma_f16(acc[mf][nf], ah[mf], bhp);
                }
        }
    }

    int g = lane >> 2, tI = lane & 3;
#pragma unroll
    for (int mf = 0; mf < 4; mf++) {
        int r0 = bm + wm + mf * 16 + g;
#pragma unroll
        for (int nf = 0; nf < 4; nf++) {
            int col = bn + wn + nf * 8 + tI * 2;
            *(__half2*)(C + (long)r0 * N + col)       = __floats2half2_rn(acc[mf][nf][0], acc[mf][nf][1]);
            *(__half2*)(C + (long)(r0 + 8) * N + col) = __floats2half2_rn(acc[mf][nf][2], acc[mf][nf][3]);
        }
    }
}

// ---------------- HMMA x_dbl GEMM (A fp16, B hi/lo 2-term) ------------------
#define RS80 80
#define MAT_B (128 * RS80)
#define X_OFF_A  0
#define X_OFF_BH (MAT_B)
#define X_OFF_BL (2 * MAT_B)
#define X_STAGE (3 * MAT_B)     // 30720
#define X_GSMEM (2 * X_STAGE)   // 61440

__global__ void __launch_bounds__(256)
k_gemm_xdbl_h() {
    int z = blockIdx.y;
    int kk = z & 7;
    if (g_gw[z] == 0.f) return;
    const int K = 2048;
    const __half* A  = g_uh + (long)z * 256 * 2048;
    const __half* Bh = g_xpwh + (long)kk * 96 * 2048;
    const __half* Bl = g_xpwl + (long)kk * 96 * 2048;
    float* C = g_xdbl + (long)z * 256 * 96;
    __half* Dh = g_xdh + (long)z * 256 * 64;

    int bm = blockIdx.x * 128;
    A += (long)bm * K;

    extern __shared__ char dsm[];
    unsigned sb0 = smem_u32(dsm);
    int tid = threadIdx.x;
    int lane = tid & 31, warp = tid >> 5;
    int wm = (warp & 1) * 64, wn = (warp >> 1) * 24;
    int mi = lane >> 3, lr = lane & 7;
    int arow = (mi & 1) * 8 + lr;
    int akb  = (mi >> 1) * 16;
    int brow = (mi >> 1) * 8 + lr;
    int bkb  = (mi & 1) * 16;

    float acc[4][3][4];
#pragma unroll
    for (int i = 0; i < 4; i++)
#pragma unroll
        for (int j = 0; j < 3; j++)
#pragma unroll
            for (int r = 0; r < 4; r++) acc[i][j][r] = 0.f;

    int ci0 = tid * 2;
    int row0 = ci0 >> 2, kc0 = (ci0 & 3);
    int row1 = (ci0 + 1) >> 2, kc1 = ((ci0 + 1) & 3);
    int rb0 = row0 < 96 ? row0 : 95;
    int rb1 = row1 < 96 ? row1 : 95;

#define XISSUE(J, BUF)                                                                       \
    {                                                                                        \
        int k0 = (J) << 5;                                                                   \
        unsigned sbs = sb0 + (BUF) * X_STAGE;                                                \
        cp16(sbs + X_OFF_A  + row0 * RS80 + kc0 * 16, A  + (long)row0 * K + k0 + kc0 * 8);   \
        cp16(sbs + X_OFF_A  + row1 * RS80 + kc1 * 16, A  + (long)row1 * K + k0 + kc1 * 8);   \
        cp16(sbs + X_OFF_BH + row0 * RS80 + kc0 * 16, Bh + (long)rb0 * K + k0 + kc0 * 8);    \
        cp16(sbs + X_OFF_BH + row1 * RS80 + kc1 * 16, Bh + (long)rb1 * K + k0 + kc1 * 8);    \
        cp16(sbs + X_OFF_BL + row0 * RS80 + kc0 * 16, Bl + (long)rb0 * K + k0 + kc0 * 8);    \
        cp16(sbs + X_OFF_BL + row1 * RS80 + kc1 * 16, Bl + (long)rb1 * K + k0 + kc1 * 8);    \
        cp_commit();                                                                         \
    }

    const int nk = 64;
    XISSUE(0, 0);
    for (int j = 0; j < nk; j++) {
        if (j + 1 < nk) { XISSUE(j + 1, (j + 1) & 1); cp_wait<1>(); }
        else            { cp_wait<0>(); }
        __syncthreads();
        unsigned sbs = sb0 + (j & 1) * X_STAGE;
#pragma unroll
        for (int ks = 0; ks < 2; ks++) {
            unsigned kb = ks * 32;
            unsigned ah[4][4];
#pragma unroll
            for (int mf = 0; mf < 4; mf++) {
                unsigned ro = (wm + mf * 16 + arow) * RS80 + kb + akb;
                ldmx4(ah[mf], sbs + X_OFF_A + ro);
            }
            unsigned bh[2][4], bl[2][4];
#pragma unroll
            for (int p = 0; p < 2; p++) {
                unsigned ro = (wn + p * 16 + brow) * RS80 + kb + bkb;
                ldmx4(bh[p], sbs + X_OFF_BH + ro);
                ldmx4(bl[p], sbs + X_OFF_BL + ro);
            }
#pragma unroll
            for (int mf = 0; mf < 4; mf++)
#pragma unroll
                for (int nf = 0; nf < 3; nf++) {
                    const unsigned* bhp = &bh[nf >> 1][(nf & 1) * 2];
                    const unsigned* blp = &bl[nf >> 1][(nf & 1) * 2];
                    mma_f16(acc[mf][nf], ah[mf], bhp);
                    mma_f16(acc[mf][nf], ah[mf], blp);
                }
        }
        __syncthreads();
    }

    int g = lane >> 2, tI = lane & 3;
#pragma unroll
    for (int mf = 0; mf < 4; mf++) {
        int r0 = bm + wm + mf * 16 + g;
#pragma unroll
        for (int nf = 0; nf < 3; nf++) {
            int col = wn + nf * 8 + tI * 2;
#pragma unroll
            for (int half = 0; half < 2; half++) {
                int r = r0 + half * 8;
                float v0 = acc[mf][nf][half * 2 + 0];
                float v1 = acc[mf][nf][half * 2 + 1];
                C[(long)r * 96 + col]     = v0;
                C[(long)r * 96 + col + 1] = v1;
                if (col < 64) {
                    Dh[(long)r * 64 + col]     = __float2half(v0);
                    Dh[(long)r * 64 + col + 1] = __float2half(v1);
                }
            }
        }
    }
}

// ---------------- HMMA dt GEMM (plain fp16, K=64, fp16 out) -----------------
#define D_OFF_A 0
#define D_OFF_B (MAT_B)
#define D_STAGE (2 * MAT_B)     // 20480
#define D_GSMEM (2 * D_STAGE)   // 40960

__global__ void __launch_bounds__(256)
k_gemm_dt_h(const float* __restrict__ bias) {
    int z = blockIdx.z;
    int kk = z & 7;
    if (g_gw[z] == 0.f) return;
    const int K = 64, N = 2048;
    const __half* A = g_xdh + (long)z * 256 * 64;
    const __half* B = g_dtwh + (long)kk * 2048 * 64;
    __half* C = g_dtf + (long)z * 256 * 2048;

    int bm = blockIdx.y * 128, bn = blockIdx.x * 128;
    A += (long)bm * K;
    B += (long)bn * K;

    extern __shared__ char dsm[];
    unsigned sb0 = smem_u32(dsm);
    int tid = threadIdx.x;
    int lane = tid & 31, warp = tid >> 5;
    int wm = (warp & 1) * 64, wn = (warp >> 1) * 32;
    int mi = lane >> 3, lr = lane & 7;
    int arow = (mi & 1) * 8 + lr;
    int akb  = (mi >> 1) * 16;
    int brow = (mi >> 1) * 8 + lr;
    int bkb  = (mi & 1) * 16;

    float acc[4][4][4];
#pragma unroll
    for (int i = 0; i < 4; i++)
#pragma unroll
        for (int j = 0; j < 4; j++)
#pragma unroll
            for (int r = 0; r < 4; r++) acc[i][j][r] = 0.f;

    int ci0 = tid * 2;
    int row0 = ci0 >> 2, kc0 = (ci0 & 3);
    int row1 = (ci0 + 1) >> 2, kc1 = ((ci0 + 1) & 3);

#define DISSUE(J, BUF)                                                                      \
    {                                                                                       \
        int k0 = (J) << 5;                                                                  \
        unsigned sbs = sb0 + (BUF) * D_STAGE;                                               \
        cp16(sbs + D_OFF_A + row0 * RS80 + kc0 * 16, A + (long)row0 * K + k0 + kc0 * 8);    \
        cp16(sbs + D_OFF_A + row1 * RS80 + kc1 * 16, A + (long)row1 * K + k0 + kc1 * 8);    \
        cp16(sbs + D_OFF_B + row0 * RS80 + kc0 * 16, B + (long)row0 * K + k0 + kc0 * 8);    \
        cp16(sbs + D_OFF_B + row1 * RS80 + kc1 * 16, B + (long)row1 * K + k0 + kc1 * 8);    \
        cp_commit();                                                                        \
    }

    DISSUE(0, 0);
    DISSUE(1, 1);
    cp_wait<0>();
    __syncthreads();

#pragma unroll
    for (int j = 0; j < 2; j++) {
        unsigned sbs = sb0 + j * D_STAGE;
#pragma unroll
        for (int ks = 0; ks < 2; ks++) {
            unsigned kb = ks * 32;
            unsigned ah[4][4];
#pragma unroll
            for (int mf = 0; mf < 4; mf++) {
                unsigned ro = (wm + mf * 16 + arow) * RS80 + kb + akb;
                ldmx4(ah[mf], sbs + D_OFF_A + ro);
            }
            unsigned bh[2][4];
#pragma unroll
            for (int p = 0; p < 2; p++) {
                unsigned ro = (wn + p * 16 + brow) * RS80 + kb + bkb;
                ldmx4(bh[p], sbs + D_OFF_B + ro);
            }
#pragma unroll
            for (int mf = 0; mf < 4; mf++)
#pragma unroll
                for (int nf = 0; nf < 4; nf++) {
                    const unsigned* bhp = &bh[nf >> 1][(nf & 1) * 2];
                    mma_f16(acc[mf][nf], ah[mf], bhp);
                }
        }
    }

    int g = lane >> 2, tI = lane & 3;
#pragma unroll
    for (int mf = 0; mf < 4; mf++) {
        int r0 = bm + wm + mf * 16 + g;
#pragma unroll
        for (int nf = 0; nf < 4; nf++) {
            int col = bn + wn + nf * 8 + tI * 2;
            float b0 = bias[kk * N + col], b1 = bias[kk * N + col + 1];
#pragma unroll
            for (int half = 0; half < 2; half++) {
                int r = r0 + half * 8;
                float v0 = acc[mf][nf][half * 2 + 0] + b0;
                float v1 = acc[mf][nf][half * 2 + 1] + b1;
                v0 = (v0 > 20.f) ? v0 : log1pf(__expf(v0));
                v1 = (v1 > 20.f) ? v1 : log1pf(__expf(v1));
                C[(long)r * N + col]     = __float2half(v0);
                C[(long)r * N + col + 1] = __float2half(v1);
            }
        }
    }
}

// ---------------- depthwise causal conv (l-parallel, fp16 in/out) -----------
__global__ void k_conv(const float* __restrict__ cw, const float* __restrict__ cb) {
    int gb = blockIdx.x;
    int l = gb & 255, z = gb >> 8;
    int k = z & 7;
    if (g_gw[z] == 0.f) return;
    const __half* xzb = g_xzf + (long)z * 256 * 4096;
    long ubase = ((long)z * 256 + l) * 2048;
#pragma unroll
    for (int i = 0; i < 8; i++) {
        int d = threadIdx.x + i * 256;
        float4 w4 = ((const float4*)cw)[k * 2048 + d];
        float acc = cb[k * 2048 + d];
        float wv[4] = {w4.x, w4.y, w4.z, w4.w};
#pragma unroll
        for (int j = 0; j < 4; j++) {
            int lp = l - 3 + j;
            if (lp >= 0) acc += wv[j] * __half2float(xzb[(long)lp * 4096 + d]);
        }
        float u = acc / (1.f + __expf(-acc));  // silu
        g_uh[ubase + d] = __float2half(u);
    }
}

// ---------------- selective scan -> y2 fp16 ---------------------------------
__global__ void k_scan(const float* __restrict__ A_log, const float* __restrict__ D_p) {
    __shared__ float sbc[256 * 32];
    int gb = blockIdx.x;
    int z = gb >> 3, dblk = gb & 7;
    int k = z & 7;
    if (g_gw[z] == 0.f) return;
    for (int idx = threadIdx.x; idx < 8192; idx += 256)
        sbc[idx] = g_xdbl[((long)z * 256 + (idx >> 5)) * 96 + 64 + (idx & 31)];
    __syncthreads();
    int d = dblk * 256 + threadIdx.x;
    float a[16];
#pragma unroll
    for (int s = 0; s < 16; s++) a[s] = -__expf(A_log[(long)(k * 2048 + d) * 16 + s]);
    bool fast = true;
#pragma unroll
    for (int s = 0; s < 16; s++) {
        float r = a[s] / a[0];
        if (fabsf(r - (float)(s + 1)) > 1e-4f) fast = false;
    }
    float dp = D_p[k * 2048 + d];
    float h[16];
#pragma unroll
    for (int s = 0; s < 16; s++) h[s] = 0.f;
    const __half* dtb = g_dtf + (long)z * 256 * 2048 + d;
    const __half* uhb = g_uh + (long)z * 256 * 2048 + d;
    const __half* zb  = g_xzf + (long)z * 256 * 4096 + 2048 + d;
    long ybase = (long)z * 256 * 2048 + d;
    for (int l = 0; l < 256; l++) {
        float dt = __half2float(dtb[(long)l * 2048]);
        float uu = __half2float(uhb[(long)l * 2048]);
        float zz = __half2float(zb[(long)l * 4096]);
        float dtu = dt * uu;
        float acc = 0.f;
        const float* bc = &sbc[l * 32];
        if (fast) {
            float e = __expf(dt * a[0]);
            float p = 1.f;
#pragma unroll
            for (int s = 0; s < 16; s++) {
                p *= e;
                h[s] = p * h[s] + dtu * bc[s];
                acc += h[s] * bc[16 + s];
            }
        } else {
#pragma unroll
            for (int s = 0; s < 16; s++) {
                float e = __expf(dt * a[s]);
                h[s] = e * h[s] + dtu * bc[s];
                acc += h[s] * bc[16 + s];
            }
        }
        float y = acc + uu * dp;
        y *= zz / (1.f + __expf(-zz));  // * silu(z)
        g_y2f[ybase + (long)l * 2048] = __float2half(y);
    }
}

// ---------------- cross-merge (2 outputs/thread, __half2 gathers) -----------
__global__ void k_merge2(float* __restrict__ out) {
    int t = blockIdx.x * 256 + threadIdx.x;     // 1,048,576 threads, 2 outputs each
    int pix = t & 255, c2 = (t >> 8) & 511, b = t >> 17;
    int c = c2 * 2;
    int h = pix >> 4, w = pix & 15;
    int l0 = pix;
    int l1 = w * 16 + h;
    int ld = ((w - h) & 15) * 16 + h;
    int la = ((w + h) & 15) * 16 + h;
    int pos[8] = {l0, l1, 255 - l0, 255 - l1, ld, la, 255 - ld, 255 - la};
    float a0 = 0.f, a1 = 0.f;
#pragma unroll
    for (int k = 0; k < 8; k++) {
        float g = g_gw[b * 8 + k];
        if (g != 0.f) {
            __half2 v = *(const __half2*)&g_ysf[((long)(b * 8 + k) * 256 + pos[k]) * 1024 + c];
            float2 f = __half22float2(v);
            a0 += g * f.x;
            a1 += g * f.y;
        }
    }
    long ob = (long)b * 1024 * 256 + pix;
    out[ob + (long)c * 256]       = a0;
    out[ob + (long)(c + 1) * 256] = a1;
}

// ---------------- launch ----------------
extern "C" void kernel_launch(void* const* d_in, const int* in_sizes, int n_in,
                              void* d_out, int out_size) {
    const float* x        = (const float*)d_in[0];
    const float* pw       = (const float*)d_in[1];
    const float* bn_g     = (const float*)d_in[2];
    const float* bn_b     = (const float*)d_in[3];
    const float* gate_w   = (const float*)d_in[4];
    const float* ln_g     = (const float*)d_in[5];
    const float* ln_b     = (const float*)d_in[6];
    const float* fd_scale = (const float*)d_in[7];
    const float* in_w     = (const float*)d_in[8];
    const float* cw       = (const float*)d_in[9];
    const float* cb       = (const float*)d_in[10];
    const float* xp_w     = (const float*)d_in[11];
    const float* dtp_w    = (const float*)d_in[12];
    const float* dtp_b    = (const float*)d_in[13];
    const float* A_log    = (const float*)d_in[14];
    const float* D_p      = (const float*)d_in[15];
    const float* out_w    = (const float*)d_in[16];
    float* out = (float*)d_out;

    cudaFuncSetAttribute(k_gemm_h, cudaFuncAttributeMaxDynamicSharedMemorySize, G_SMEM);
    cudaFuncSetAttribute(k_gemm_xdbl_h, cudaFuncAttributeMaxDynamicSharedMemorySize, X_GSMEM);
    cudaFuncSetAttribute(k_gemm_dt_h, cudaFuncAttributeMaxDynamicSharedMemorySize, D_GSMEM);

    // fused weight conversions (one launch)
    {
        long blocks = (SP_TOT + 255) / 256;
        k_split_all<<<(unsigned)blocks, 256>>>((const float4*)in_w, (const float4*)out_w,
                                               xp_w, dtp_w);
    }

    k_pool<<<8 * 512, 288>>>(x);
    // all four CBR variants in ONE launch (144 blocks)
    k_cbr_all<<<144, 256>>>(x, pw, bn_g, bn_b);
    k_p0_reduce<<<8 * 128, 256>>>();
    k_assemble<<<8 * 256, 256>>>(x);
    k_gate_weights<<<8, 1024>>>(gate_w);
    k_fdgate<<<8 * 8 * 256, 256>>>(ln_g, ln_b, fd_scale);

    // in_proj (fp16 HMMA, K-chunk 64, fp16 out)
    { dim3 g(32, 2, 64); k_gemm_h<<<g, 256, G_SMEM>>>(0, 4096, 1024); }
    // depthwise conv + silu -> u fp16 (l-parallel)
    k_conv<<<64 * 256, 256>>>(cw, cb);
    // x_dbl (HMMA, A fp16 + B hi/lo 2-term)
    { dim3 g(2, 64); k_gemm_xdbl_h<<<g, 256, X_GSMEM>>>(); }
    // dt projection + softplus (plain fp16 HMMA)
    { dim3 g(16, 2, 64); k_gemm_dt_h<<<g, 256, D_GSMEM>>>(dtp_b); }
    // selective scan
    k_scan<<<64 * 8, 256>>>(A_log, D_p);
    // out_proj (fp16 HMMA, K-chunk 64, fp16 out)
    { dim3 g(8, 2, 64); k_gemm_h<<<g, 256, G_SMEM>>>(1, 1024, 2048); }
    // cross-merge (2 outputs/thread)
    k_merge2<<<4096, 256>>>(out);
}